// round 10
// baseline (speedup 1.0000x reference)
#include <cuda_runtime.h>
#include <cstdint>

#define HID 1024
#define SEQ 1024
#define NB  4
#define NH  16
#define DH  64

// Scratch for q1,k1,v1,q2,k2,v2 : values stored ALREADY tf32-rounded.
__device__ float g_qkv[6][NB * SEQ * HID];

struct QKVArgs {
    const float* x[2];
    const float* w[6];
    const float* b[6];
};

__device__ __forceinline__ uint32_t f2tf(float x) {
    uint32_t t;
    asm("cvt.rna.tf32.f32 %0, %1;" : "=r"(t) : "f"(x));
    return t;
}

__device__ __forceinline__ void mma_tf32(float* c, const uint32_t* a, const uint32_t* b) {
    asm volatile(
        "mma.sync.aligned.m16n8k8.row.col.f32.tf32.tf32.f32 "
        "{%0,%1,%2,%3}, {%4,%5,%6,%7}, {%8,%9}, {%0,%1,%2,%3};\n"
        : "+f"(c[0]), "+f"(c[1]), "+f"(c[2]), "+f"(c[3])
        : "r"(a[0]), "r"(a[1]), "r"(a[2]), "r"(a[3]), "r"(b[0]), "r"(b[1]));
}

#define CP_ASYNC16(saddr, gptr) \
    asm volatile("cp.async.cg.shared.global [%0], [%1], 16;\n" :: "r"(saddr), "l"(gptr))
#define CP_COMMIT() asm volatile("cp.async.commit_group;\n" ::: "memory")
#define CP_WAIT(n)  asm volatile("cp.async.wait_group %0;\n" :: "n"(n) : "memory")

__device__ __forceinline__ float fast_exp(float x) {
    x = fmaxf(x, -80.f);
    float t = x * 1.44269504f;
    float r = rintf(t);
    float y = (t - r) * 0.69314718f;
    float p = 8.3333333e-3f;
    p = fmaf(p, y, 4.1666667e-2f);
    p = fmaf(p, y, 1.6666667e-1f);
    p = fmaf(p, y, 5.0e-1f);
    p = fmaf(p, y, 1.0f);
    p = fmaf(p, y, 1.0f);
    return __int_as_float(__float_as_int(p) + (((int)r) << 23));
}

// ---------------------------------------------------------------------------
// QKV projection: 128x64x32, 256 thr, double-buffered, tf32-rounded output.
// (unchanged from R7)
// ---------------------------------------------------------------------------
#define GA_PITCH 36
#define GB_PITCH 72
#define GA_WORDS (128 * GA_PITCH)
#define GB_WORDS (32 * GB_PITCH)
#define GEMM_SMEM ((2 * GA_WORDS + 2 * GB_WORDS) * 4)

__global__ __launch_bounds__(256, 2) void qkv_gemm(QKVArgs args) {
    extern __shared__ uint32_t gsm[];
    uint32_t* As = gsm;
    uint32_t* Bs = gsm + 2 * GA_WORDS;

    const int p = blockIdx.z;
    const float* X    = args.x[p / 3];
    const float* W    = args.w[p];
    const float* bias = args.b[p];
    float* C = g_qkv[p];

    const int tid = threadIdx.x;
    const int wid = tid >> 5;
    const int lane = tid & 31;
    const int ly = lane >> 2;
    const int lx = lane & 3;
    const int wm = (wid & 3) * 32;
    const int wn = (wid >> 2) * 32;
    const int bm = blockIdx.y << 7;
    const int bn = blockIdx.x << 6;

    const int arow = tid >> 3, ac4 = (tid & 7) << 2;
    const int brow = tid >> 4, bc4 = (tid & 15) << 2;

    float4 ra[4], rb[2];

#pragma unroll
    for (int i = 0; i < 4; i++)
        ra[i] = *(const float4*)(X + (size_t)(bm + arow + i * 32) * HID + ac4);
#pragma unroll
    for (int i = 0; i < 2; i++)
        rb[i] = *(const float4*)(W + (size_t)(brow + i * 16) * HID + bn + bc4);
#pragma unroll
    for (int i = 0; i < 4; i++) {
        uint4 t = {f2tf(ra[i].x), f2tf(ra[i].y), f2tf(ra[i].z), f2tf(ra[i].w)};
        *(uint4*)&As[(arow + i * 32) * GA_PITCH + ac4] = t;
    }
#pragma unroll
    for (int i = 0; i < 2; i++) {
        uint4 t = {f2tf(rb[i].x), f2tf(rb[i].y), f2tf(rb[i].z), f2tf(rb[i].w)};
        *(uint4*)&Bs[(brow + i * 16) * GB_PITCH + bc4] = t;
    }
    __syncthreads();

    float acc[2][4][4];
#pragma unroll
    for (int i = 0; i < 2; i++)
#pragma unroll
        for (int j = 0; j < 4; j++)
#pragma unroll
            for (int q = 0; q < 4; q++) acc[i][j][q] = 0.f;

    for (int k0 = 0; k0 < HID; k0 += 32) {
        const int cur = (k0 >> 5) & 1;
        const uint32_t* Ab = As + cur * GA_WORDS;
        const uint32_t* Bb = Bs + cur * GB_WORDS;
        const bool more = (k0 + 32) < HID;

        if (more) {
#pragma unroll
            for (int i = 0; i < 4; i++)
                ra[i] = *(const float4*)(X + (size_t)(bm + arow + i * 32) * HID + k0 + 32 + ac4);
#pragma unroll
            for (int i = 0; i < 2; i++)
                rb[i] = *(const float4*)(W + (size_t)(k0 + 32 + brow + i * 16) * HID + bn + bc4);
        }

#pragma unroll
        for (int ks = 0; ks < 4; ks++) {
            const int kk = ks * 8;
            uint32_t a[2][4], b[4][2];
#pragma unroll
            for (int mi = 0; mi < 2; mi++) {
                int m = wm + mi * 16;
                a[mi][0] = Ab[(m + ly) * GA_PITCH + kk + lx];
                a[mi][1] = Ab[(m + ly + 8) * GA_PITCH + kk + lx];
                a[mi][2] = Ab[(m + ly) * GA_PITCH + kk + lx + 4];
                a[mi][3] = Ab[(m + ly + 8) * GA_PITCH + kk + lx + 4];
            }
#pragma unroll
            for (int ni = 0; ni < 4; ni++) {
                int n = wn + ni * 8;
                b[ni][0] = Bb[(kk + lx) * GB_PITCH + n + ly];
                b[ni][1] = Bb[(kk + lx + 4) * GB_PITCH + n + ly];
            }
#pragma unroll
            for (int mi = 0; mi < 2; mi++)
#pragma unroll
                for (int ni = 0; ni < 4; ni++)
                    mma_tf32(acc[mi][ni], a[mi], b[ni]);
        }

        if (more) {
            uint32_t* An = As + (cur ^ 1) * GA_WORDS;
            uint32_t* Bn = Bs + (cur ^ 1) * GB_WORDS;
#pragma unroll
            for (int i = 0; i < 4; i++) {
                uint4 t = {f2tf(ra[i].x), f2tf(ra[i].y), f2tf(ra[i].z), f2tf(ra[i].w)};
                *(uint4*)&An[(arow + i * 32) * GA_PITCH + ac4] = t;
            }
#pragma unroll
            for (int i = 0; i < 2; i++) {
                uint4 t = {f2tf(rb[i].x), f2tf(rb[i].y), f2tf(rb[i].z), f2tf(rb[i].w)};
                *(uint4*)&Bn[(brow + i * 16) * GB_PITCH + bc4] = t;
            }
        }
        __syncthreads();
    }

#pragma unroll
    for (int mi = 0; mi < 2; mi++) {
#pragma unroll
        for (int ni = 0; ni < 4; ni++) {
            int m = bm + wm + mi * 16 + ly;
            int n = bn + wn + ni * 8 + 2 * lx;
            float b0 = bias[n], b1 = bias[n + 1];
            float2 v0 = {__uint_as_float(f2tf(acc[mi][ni][0] + b0)),
                         __uint_as_float(f2tf(acc[mi][ni][1] + b1))};
            float2 v1 = {__uint_as_float(f2tf(acc[mi][ni][2] + b0)),
                         __uint_as_float(f2tf(acc[mi][ni][3] + b1))};
            *(float2*)(C + (size_t)m * HID + n) = v0;
            *(float2*)(C + (size_t)(m + 8) * HID + n) = v1;
        }
    }
}

// ---------------------------------------------------------------------------
// Fused cross-attention, 16 q-rows per CTA -> 109KB smem -> 2 CTAs/SM.
// 256 threads, cp.async double-buffered 64-row K/V tiles.
// Phase1: 8 warps x n8, hoisted Q A-frags (K pitch 76, ly-indexed frags).
// Phase2: k-split (warp owns 8 k-rows/tile), V pitch 72 (lx-indexed frags),
//         8-way smem reduction.
// ---------------------------------------------------------------------------
#define QROWS     16
#define SSC_PITCH 1028
#define Q_PITCH   68
#define KPITCH    76
#define VPITCH    72
#define KV_WORDS  (64 * KPITCH)
#define RED_PITCH 68
#define ATTN_SMEM ((QROWS * SSC_PITCH + QROWS * Q_PITCH + 2 * KV_WORDS) * 4)

__global__ __launch_bounds__(256, 2) void attn_kernel(const float* __restrict__ mask1,
                                                      const float* __restrict__ mask2,
                                                      float* __restrict__ out) {
    extern __shared__ float sm[];
    float*    Ssc = sm;                                      // [16][1028]
    uint32_t* Qs  = (uint32_t*)(sm + QROWS * SSC_PITCH);     // [16][68] tf32
    uint32_t* KVs = Qs + QROWS * Q_PITCH;                    // 2 x [64][KPITCH]
    float*    red = (float*)KVs;                             // 8 x [16][68] (reused)

    const int qb = blockIdx.x;          // 0..63 (16-row blocks)
    const int h  = blockIdx.y;
    const int b  = blockIdx.z >> 1;
    const int st = blockIdx.z & 1;

    const float* Q    = g_qkv[st * 3];
    const float* K    = st ? g_qkv[1] : g_qkv[4];
    const float* V    = st ? g_qkv[2] : g_qkv[5];
    const float* mask = st ? mask1 : mask2;

    float* probs = out + 8388608 + (size_t)st * 67108864
                 + ((size_t)(b * NH + h) * SEQ + qb * QROWS) * SEQ;
    float* ctx = out + (size_t)st * 4194304;

    const int tid = threadIdx.x;
    const int wid = tid >> 5;
    const int lane = tid & 31;
    const int ly = lane >> 2;
    const int lx = lane & 3;

    // staging: 4 threads per row, 16 consecutive words (4 x cp.async16) each
    const int srow = tid >> 2;            // 0..63
    const int sbase = (tid & 3) << 4;     // word offset 0/16/32/48
    const uint32_t kv_base = (uint32_t)__cvta_generic_to_shared(KVs);

    // ---- stage Q (plain copy; already tf32) ----
    {
        int r = tid >> 4, c4 = (tid & 15) << 2;
        *(float4*)&Qs[r * Q_PITCH + c4] =
            *(const float4*)(Q + (size_t)(b * SEQ + qb * QROWS + r) * HID + h * DH + c4);
    }

    // ---- phase 1 prologue: K tile 0 (64 rows) via cp.async ----
#pragma unroll
    for (int j = 0; j < 4; j++)
        CP_ASYNC16(kv_base + (srow * KPITCH + sbase + j * 4) * 4,
                   K + (size_t)(b * SEQ + srow) * HID + h * DH + sbase + j * 4);
    CP_COMMIT();
    __syncthreads();   // Qs visible

    // hoisted Q A-fragments (rows 0..15, invariant over all K tiles)
    uint32_t aq[8][4];
#pragma unroll
    for (int ks = 0; ks < 8; ks++) {
        const int kk = ks * 8;
        aq[ks][0] = Qs[ly * Q_PITCH + kk + lx];
        aq[ks][1] = Qs[(ly + 8) * Q_PITCH + kk + lx];
        aq[ks][2] = Qs[ly * Q_PITCH + kk + lx + 4];
        aq[ks][3] = Qs[(ly + 8) * Q_PITCH + kk + lx + 4];
    }

    const int wn = wid * 8;   // each warp owns one n8 column group of the 64-col tile

    for (int kt = 0; kt < 16; kt++) {
        const int cur = kt & 1;
        if (kt < 15) {
#pragma unroll
            for (int j = 0; j < 4; j++)
                CP_ASYNC16(kv_base + ((cur ^ 1) * KV_WORDS + srow * KPITCH + sbase + j * 4) * 4,
                           K + (size_t)(b * SEQ + (kt + 1) * 64 + srow) * HID + h * DH + sbase + j * 4);
            CP_COMMIT();
            CP_WAIT(1);
        } else {
            CP_WAIT(0);
        }
        __syncthreads();

        const uint32_t* KB = KVs + cur * KV_WORDS;
        float sacc[4] = {0.f, 0.f, 0.f, 0.f};

#pragma unroll
        for (int ks = 0; ks < 8; ks++) {
            const int kk = ks * 8;
            uint32_t bb[2];
            bb[0] = KB[(wn + ly) * KPITCH + kk + lx];
            bb[1] = KB[(wn + ly) * KPITCH + kk + lx + 4];
            mma_tf32(sacc, aq[ks], bb);
        }

        {
            int col = kt * 64 + wn + 2 * lx;
            float mk0 = mask[b * SEQ + col];
            float mk1 = mask[b * SEQ + col + 1];
            Ssc[ly * SSC_PITCH + col]           = sacc[0] * 0.125f + mk0;
            Ssc[ly * SSC_PITCH + col + 1]       = sacc[1] * 0.125f + mk1;
            Ssc[(ly + 8) * SSC_PITCH + col]     = sacc[2] * 0.125f + mk0;
            Ssc[(ly + 8) * SSC_PITCH + col + 1] = sacc[3] * 0.125f + mk1;
        }
        __syncthreads();
    }

    // ---- prefetch V tile 0 (overlaps softmax), pitch 72 ----
#pragma unroll
    for (int j = 0; j < 4; j++)
        CP_ASYNC16(kv_base + (srow * VPITCH + sbase + j * 4) * 4,
                   V + (size_t)(b * SEQ + srow) * HID + h * DH + sbase + j * 4);
    CP_COMMIT();

    // ---- softmax: one warp per row, rows wid and wid+8 ----
#pragma unroll
    for (int rr = 0; rr < 2; rr++) {
        int r = wid + rr * 8;
        float* row = Ssc + r * SSC_PITCH;
        float m = -1e30f;
        for (int c = lane; c < SEQ; c += 32) m = fmaxf(m, row[c]);
#pragma unroll
        for (int o = 16; o >= 1; o >>= 1) m = fmaxf(m, __shfl_xor_sync(0xffffffffu, m, o));
        float s = 0.f;
        for (int c = lane; c < SEQ; c += 32) {
            float e = fast_exp(row[c] - m);
            row[c] = e;
            s += e;
        }
#pragma unroll
        for (int o = 16; o >= 1; o >>= 1) s += __shfl_xor_sync(0xffffffffu, s, o);
        float inv = 1.f / s;
        for (int c = lane; c < SEQ; c += 32) row[c] *= inv;
    }
    __syncthreads();

    // ---- write probs (coalesced f4) + convert P to tf32 in place ----
    for (int i = tid; i < QROWS * 256; i += 256) {
        int row = i >> 8, c4 = (i & 255) << 2;
        float4 v = *(float4*)&Ssc[row * SSC_PITCH + c4];
        *(float4*)&probs[row * 1024 + c4] = v;
        uint4 t = {f2tf(v.x), f2tf(v.y), f2tf(v.z), f2tf(v.w)};
        *(uint4*)&Ssc[row * SSC_PITCH + c4] = t;
    }

    // ---- Phase 2: ctx = P @ V, k-split (warp owns 8 k-rows of each tile) ----
    float cacc[8][4];
#pragma unroll
    for (int ni = 0; ni < 8; ni++)
#pragma unroll
        for (int q = 0; q < 4; q++) cacc[ni][q] = 0.f;

    const uint32_t* Su = (const uint32_t*)Ssc;

    for (int vt = 0; vt < 16; vt++) {
        const int cur = vt & 1;
        if (vt < 15) {
#pragma unroll
            for (int j = 0; j < 4; j++)
                CP_ASYNC16(kv_base + ((cur ^ 1) * KV_WORDS + srow * VPITCH + sbase + j * 4) * 4,
                           V + (size_t)(b * SEQ + (vt + 1) * 64 + srow) * HID + h * DH + sbase + j * 4);
            CP_COMMIT();
            CP_WAIT(1);
        } else {
            CP_WAIT(0);
        }
        __syncthreads();

        const uint32_t* VB = KVs + cur * KV_WORDS;
        const int kloc = wid * 8;            // this warp's k-rows in the tile
        const int kg = vt * 64 + kloc;

        uint32_t a[4];
        a[0] = Su[ly * SSC_PITCH + kg + lx];
        a[1] = Su[(ly + 8) * SSC_PITCH + kg + lx];
        a[2] = Su[ly * SSC_PITCH + kg + lx + 4];
        a[3] = Su[(ly + 8) * SSC_PITCH + kg + lx + 4];

#pragma unroll
        for (int ni = 0; ni < 8; ni++) {
            uint32_t bb[2];
            bb[0] = VB[(kloc + lx) * VPITCH + ni * 8 + ly];
            bb[1] = VB[(kloc + lx + 4) * VPITCH + ni * 8 + ly];
            mma_tf32(cacc[ni], a, bb);
        }
        __syncthreads();
    }

    // ---- reduce partial ctx across the 8 warps (KV region reused) ----
#pragma unroll
    for (int ni = 0; ni < 8; ni++)
#pragma unroll
        for (int q = 0; q < 4; q++) {
            int row = ly + (q >> 1) * 8;
            int col = ni * 8 + 2 * lx + (q & 1);
            red[wid * (QROWS * RED_PITCH) + row * RED_PITCH + col] = cacc[ni][q];
        }
    __syncthreads();

    {
        int row = tid >> 4;              // 0..15
        int col = (tid & 15) << 2;       // 0..60
        float s0 = 0.f, s1 = 0.f, s2 = 0.f, s3 = 0.f;
#pragma unroll
        for (int w = 0; w < 8; w++) {
            const float* rp = red + w * (QROWS * RED_PITCH) + row * RED_PITCH + col;
            s0 += rp[0]; s1 += rp[1]; s2 += rp[2]; s3 += rp[3];
        }
        float4 v = {s0, s1, s2, s3};
        *(float4*)(ctx + (size_t)(b * SEQ + qb * QROWS + row) * HID + h * DH + col) = v;
    }
}

// ---------------------------------------------------------------------------
extern "C" void kernel_launch(void* const* d_in, const int* in_sizes, int n_in,
                              void* d_out, int out_size) {
    (void)in_sizes; (void)n_in; (void)out_size;

    const float* m1 = (const float*)d_in[1];
    const float* m2 = (const float*)d_in[3];

    QKVArgs a;
    a.x[0] = (const float*)d_in[0];
    a.x[1] = (const float*)d_in[2];
    for (int i = 0; i < 6; i++) {
        a.w[i] = (const float*)d_in[4 + 2 * i];
        a.b[i] = (const float*)d_in[5 + 2 * i];
    }

    cudaFuncSetAttribute(qkv_gemm, cudaFuncAttributeMaxDynamicSharedMemorySize,
                         GEMM_SMEM);
    cudaFuncSetAttribute(attn_kernel, cudaFuncAttributeMaxDynamicSharedMemorySize,
                         ATTN_SMEM);

    qkv_gemm<<<dim3(16, 32, 6), 256, GEMM_SMEM>>>(a);
    attn_kernel<<<dim3(64, 16, 8), 256, ATTN_SMEM>>>(m1, m2, (float*)d_out);
}

// round 12
// speedup vs baseline: 1.4963x; 1.4963x over previous
#include <cuda_runtime.h>
#include <cstdint>

#define HID 1024
#define SEQ 1024
#define NB  4
#define NH  16
#define DH  64

// Scratch for q1,k1,v1,q2,k2,v2 : values stored ALREADY tf32-rounded.
__device__ float g_qkv[6][NB * SEQ * HID];

struct QKVArgs {
    const float* x[2];
    const float* w[6];
    const float* b[6];
};

__device__ __forceinline__ uint32_t f2tf(float x) {
    uint32_t t;
    asm("cvt.rna.tf32.f32 %0, %1;" : "=r"(t) : "f"(x));
    return t;
}

__device__ __forceinline__ void mma_tf32(float* c, const uint32_t* a, const uint32_t* b) {
    asm volatile(
        "mma.sync.aligned.m16n8k8.row.col.f32.tf32.tf32.f32 "
        "{%0,%1,%2,%3}, {%4,%5,%6,%7}, {%8,%9}, {%0,%1,%2,%3};\n"
        : "+f"(c[0]), "+f"(c[1]), "+f"(c[2]), "+f"(c[3])
        : "r"(a[0]), "r"(a[1]), "r"(a[2]), "r"(a[3]), "r"(b[0]), "r"(b[1]));
}

#define CP_ASYNC16(saddr, gptr) \
    asm volatile("cp.async.cg.shared.global [%0], [%1], 16;\n" :: "r"(saddr), "l"(gptr))
#define CP_COMMIT() asm volatile("cp.async.commit_group;\n" ::: "memory")
#define CP_WAIT(n)  asm volatile("cp.async.wait_group %0;\n" :: "n"(n) : "memory")

__device__ __forceinline__ float fast_exp(float x) {
    x = fmaxf(x, -80.f);
    float t = x * 1.44269504f;
    float r = rintf(t);
    float y = (t - r) * 0.69314718f;
    float p = 8.3333333e-3f;
    p = fmaf(p, y, 4.1666667e-2f);
    p = fmaf(p, y, 1.6666667e-1f);
    p = fmaf(p, y, 5.0e-1f);
    p = fmaf(p, y, 1.0f);
    p = fmaf(p, y, 1.0f);
    return __int_as_float(__float_as_int(p) + (((int)r) << 23));
}

// ---------------------------------------------------------------------------
// QKV projection: 128x64x32, 256 thr, double-buffered, tf32-rounded output.
// (unchanged from R7)
// ---------------------------------------------------------------------------
#define GA_PITCH 36
#define GB_PITCH 72
#define GA_WORDS (128 * GA_PITCH)
#define GB_WORDS (32 * GB_PITCH)
#define GEMM_SMEM ((2 * GA_WORDS + 2 * GB_WORDS) * 4)

__global__ __launch_bounds__(256, 2) void qkv_gemm(QKVArgs args) {
    extern __shared__ uint32_t gsm[];
    uint32_t* As = gsm;
    uint32_t* Bs = gsm + 2 * GA_WORDS;

    const int p = blockIdx.z;
    const float* X    = args.x[p / 3];
    const float* W    = args.w[p];
    const float* bias = args.b[p];
    float* C = g_qkv[p];

    const int tid = threadIdx.x;
    const int wid = tid >> 5;
    const int lane = tid & 31;
    const int ly = lane >> 2;
    const int lx = lane & 3;
    const int wm = (wid & 3) * 32;
    const int wn = (wid >> 2) * 32;
    const int bm = blockIdx.y << 7;
    const int bn = blockIdx.x << 6;

    const int arow = tid >> 3, ac4 = (tid & 7) << 2;
    const int brow = tid >> 4, bc4 = (tid & 15) << 2;

    float4 ra[4], rb[2];

#pragma unroll
    for (int i = 0; i < 4; i++)
        ra[i] = *(const float4*)(X + (size_t)(bm + arow + i * 32) * HID + ac4);
#pragma unroll
    for (int i = 0; i < 2; i++)
        rb[i] = *(const float4*)(W + (size_t)(brow + i * 16) * HID + bn + bc4);
#pragma unroll
    for (int i = 0; i < 4; i++) {
        uint4 t = {f2tf(ra[i].x), f2tf(ra[i].y), f2tf(ra[i].z), f2tf(ra[i].w)};
        *(uint4*)&As[(arow + i * 32) * GA_PITCH + ac4] = t;
    }
#pragma unroll
    for (int i = 0; i < 2; i++) {
        uint4 t = {f2tf(rb[i].x), f2tf(rb[i].y), f2tf(rb[i].z), f2tf(rb[i].w)};
        *(uint4*)&Bs[(brow + i * 16) * GB_PITCH + bc4] = t;
    }
    __syncthreads();

    float acc[2][4][4];
#pragma unroll
    for (int i = 0; i < 2; i++)
#pragma unroll
        for (int j = 0; j < 4; j++)
#pragma unroll
            for (int q = 0; q < 4; q++) acc[i][j][q] = 0.f;

    for (int k0 = 0; k0 < HID; k0 += 32) {
        const int cur = (k0 >> 5) & 1;
        const uint32_t* Ab = As + cur * GA_WORDS;
        const uint32_t* Bb = Bs + cur * GB_WORDS;
        const bool more = (k0 + 32) < HID;

        if (more) {
#pragma unroll
            for (int i = 0; i < 4; i++)
                ra[i] = *(const float4*)(X + (size_t)(bm + arow + i * 32) * HID + k0 + 32 + ac4);
#pragma unroll
            for (int i = 0; i < 2; i++)
                rb[i] = *(const float4*)(W + (size_t)(k0 + 32 + brow + i * 16) * HID + bn + bc4);
        }

#pragma unroll
        for (int ks = 0; ks < 4; ks++) {
            const int kk = ks * 8;
            uint32_t a[2][4], b[4][2];
#pragma unroll
            for (int mi = 0; mi < 2; mi++) {
                int m = wm + mi * 16;
                a[mi][0] = Ab[(m + ly) * GA_PITCH + kk + lx];
                a[mi][1] = Ab[(m + ly + 8) * GA_PITCH + kk + lx];
                a[mi][2] = Ab[(m + ly) * GA_PITCH + kk + lx + 4];
                a[mi][3] = Ab[(m + ly + 8) * GA_PITCH + kk + lx + 4];
            }
#pragma unroll
            for (int ni = 0; ni < 4; ni++) {
                int n = wn + ni * 8;
                b[ni][0] = Bb[(kk + lx) * GB_PITCH + n + ly];
                b[ni][1] = Bb[(kk + lx + 4) * GB_PITCH + n + ly];
            }
#pragma unroll
            for (int mi = 0; mi < 2; mi++)
#pragma unroll
                for (int ni = 0; ni < 4; ni++)
                    mma_tf32(acc[mi][ni], a[mi], b[ni]);
        }

        if (more) {
            uint32_t* An = As + (cur ^ 1) * GA_WORDS;
            uint32_t* Bn = Bs + (cur ^ 1) * GB_WORDS;
#pragma unroll
            for (int i = 0; i < 4; i++) {
                uint4 t = {f2tf(ra[i].x), f2tf(ra[i].y), f2tf(ra[i].z), f2tf(ra[i].w)};
                *(uint4*)&An[(arow + i * 32) * GA_PITCH + ac4] = t;
            }
#pragma unroll
            for (int i = 0; i < 2; i++) {
                uint4 t = {f2tf(rb[i].x), f2tf(rb[i].y), f2tf(rb[i].z), f2tf(rb[i].w)};
                *(uint4*)&Bn[(brow + i * 16) * GB_PITCH + bc4] = t;
            }
        }
        __syncthreads();
    }

#pragma unroll
    for (int mi = 0; mi < 2; mi++) {
#pragma unroll
        for (int ni = 0; ni < 4; ni++) {
            int m = bm + wm + mi * 16 + ly;
            int n = bn + wn + ni * 8 + 2 * lx;
            float b0 = bias[n], b1 = bias[n + 1];
            float2 v0 = {__uint_as_float(f2tf(acc[mi][ni][0] + b0)),
                         __uint_as_float(f2tf(acc[mi][ni][1] + b1))};
            float2 v1 = {__uint_as_float(f2tf(acc[mi][ni][2] + b0)),
                         __uint_as_float(f2tf(acc[mi][ni][3] + b1))};
            *(float2*)(C + (size_t)m * HID + n) = v0;
            *(float2*)(C + (size_t)(m + 8) * HID + n) = v1;
        }
    }
}

// ---------------------------------------------------------------------------
// Fused cross-attention: REGISTER-RESIDENT scores. 16 q-rows/CTA, 256 thr,
// ~94KB smem -> 2 CTAs/SM. Warp w owns score cols {w*8 + 64j}. Softmax on
// registers + tiny smem reduce. P reused as mma A via per-warp smem patch.
// ---------------------------------------------------------------------------
#define QROWS   16
#define KPITCH  76
#define VPITCH  72
#define KV_WORDS (128 * KPITCH)
#define QPITCH  68
#define PWPITCH 18
#define RED_PITCH 68

#define SM_QS   (2 * KV_WORDS)
#define SM_MSK  (SM_QS + QROWS * QPITCH)
#define SM_SRED (SM_MSK + 1024)
#define SM_PW   (SM_SRED + 128)
#define ATTN_FLOATS (SM_PW + 8 * QROWS * PWPITCH)
#define ATTN_SMEM (ATTN_FLOATS * 4)

__global__ __launch_bounds__(256, 2) void attn_kernel(const float* __restrict__ mask1,
                                                      const float* __restrict__ mask2,
                                                      float* __restrict__ out) {
    extern __shared__ float sm[];
    uint32_t* KVs = (uint32_t*)sm;             // 2 x [128][KPITCH]
    uint32_t* Qs  = (uint32_t*)(sm + SM_QS);   // [16][QPITCH]
    float*    msk = sm + SM_MSK;               // [1024]
    float*    sred = sm + SM_SRED;             // [16][8]
    uint32_t* Pw  = (uint32_t*)(sm + SM_PW);   // 8 x [16][PWPITCH]
    float*    red = sm;                        // overlay on KVs for ctx reduce

    const int qb = blockIdx.x;          // 0..63
    const int h  = blockIdx.y;
    const int b  = blockIdx.z >> 1;
    const int st = blockIdx.z & 1;

    const float* Q    = g_qkv[st * 3];
    const float* K    = st ? g_qkv[1] : g_qkv[4];
    const float* V    = st ? g_qkv[2] : g_qkv[5];
    const float* mask = st ? mask1 : mask2;

    float* probs = out + 8388608 + (size_t)st * 67108864
                 + ((size_t)(b * NH + h) * SEQ + qb * QROWS) * SEQ;
    float* ctx = out + (size_t)st * 4194304;

    const int tid = threadIdx.x;
    const int wid = tid >> 5;
    const int lane = tid & 31;
    const int ly = lane >> 2;
    const int lx = lane & 3;
    const int wn8 = wid * 8;

    const int srow = tid >> 4;              // 0..15 (K/V rows srow + i*16)
    const int sc4 = (tid & 15) << 2;
    const uint32_t smb = (uint32_t)__cvta_generic_to_shared(sm);

    // ---- group 0: mask (ALL 1024 words) + Q + K tile 0 ----
    CP_ASYNC16(smb + (SM_MSK + tid * 4) * 4, mask + b * SEQ + tid * 4);
    CP_ASYNC16(smb + (SM_QS + srow * QPITCH + sc4) * 4,
               Q + (size_t)(b * SEQ + qb * QROWS + srow) * HID + h * DH + sc4);
#pragma unroll
    for (int i = 0; i < 8; i++)
        CP_ASYNC16(smb + ((srow + i * 16) * KPITCH + sc4) * 4,
                   K + (size_t)(b * SEQ + srow + i * 16) * HID + h * DH + sc4);
    CP_COMMIT();

    float acc[16][4];
#pragma unroll
    for (int j = 0; j < 16; j++)
#pragma unroll
        for (int q = 0; q < 4; q++) acc[j][q] = 0.f;

    uint32_t aq[8][4];

    // ---- Phase 1: S = Q K^T (scores stay in registers) ----
#pragma unroll
    for (int kt = 0; kt < 8; kt++) {
        if (kt < 7) {
#pragma unroll
            for (int i = 0; i < 8; i++)
                CP_ASYNC16(smb + (((kt + 1) & 1) * KV_WORDS + (srow + i * 16) * KPITCH + sc4) * 4,
                           K + (size_t)(b * SEQ + (kt + 1) * 128 + srow + i * 16) * HID + h * DH + sc4);
            CP_COMMIT();
            CP_WAIT(1);
        } else {
            CP_WAIT(0);
        }
        __syncthreads();

        if (kt == 0) {
#pragma unroll
            for (int ks = 0; ks < 8; ks++) {
                const int kk = ks * 8;
                aq[ks][0] = Qs[ly * QPITCH + kk + lx];
                aq[ks][1] = Qs[(ly + 8) * QPITCH + kk + lx];
                aq[ks][2] = Qs[ly * QPITCH + kk + lx + 4];
                aq[ks][3] = Qs[(ly + 8) * QPITCH + kk + lx + 4];
            }
        }

        const uint32_t* KB = KVs + (kt & 1) * KV_WORDS;
#pragma unroll
        for (int jj = 0; jj < 2; jj++) {
            const int nl = jj * 64 + wn8;
#pragma unroll
            for (int ks = 0; ks < 8; ks++) {
                const int kk = ks * 8;
                uint32_t bb[2];
                bb[0] = KB[(nl + ly) * KPITCH + kk + lx];
                bb[1] = KB[(nl + ly) * KPITCH + kk + lx + 4];
                mma_tf32(acc[2 * kt + jj], aq[ks], bb);
            }
        }
        __syncthreads();
    }

    // ---- prefetch V tile 0 (overlaps softmax) ----
#pragma unroll
    for (int i = 0; i < 8; i++)
        CP_ASYNC16(smb + ((srow + i * 16) * VPITCH + sc4) * 4,
                   V + (size_t)(b * SEQ + srow + i * 16) * HID + h * DH + sc4);
    CP_COMMIT();

    // ---- scale + mask (in registers) ----
#pragma unroll
    for (int j = 0; j < 16; j++) {
        const int col = wn8 + 64 * j + 2 * lx;
        float mk0 = msk[col], mk1 = msk[col + 1];
        acc[j][0] = fmaf(acc[j][0], 0.125f, mk0);
        acc[j][1] = fmaf(acc[j][1], 0.125f, mk1);
        acc[j][2] = fmaf(acc[j][2], 0.125f, mk0);
        acc[j][3] = fmaf(acc[j][3], 0.125f, mk1);
    }

    // ---- softmax on registers ----
    float m0 = -1e30f, m1 = -1e30f;
#pragma unroll
    for (int j = 0; j < 16; j++) {
        m0 = fmaxf(m0, fmaxf(acc[j][0], acc[j][1]));
        m1 = fmaxf(m1, fmaxf(acc[j][2], acc[j][3]));
    }
    m0 = fmaxf(m0, __shfl_xor_sync(0xffffffffu, m0, 1));
    m0 = fmaxf(m0, __shfl_xor_sync(0xffffffffu, m0, 2));
    m1 = fmaxf(m1, __shfl_xor_sync(0xffffffffu, m1, 1));
    m1 = fmaxf(m1, __shfl_xor_sync(0xffffffffu, m1, 2));
    if (lx == 0) {
        sred[ly * 8 + wid] = m0;
        sred[(ly + 8) * 8 + wid] = m1;
    }
    __syncthreads();
    {
        float4 a4 = *(float4*)&sred[ly * 8];
        float4 b4 = *(float4*)&sred[ly * 8 + 4];
        m0 = fmaxf(fmaxf(fmaxf(a4.x, a4.y), fmaxf(a4.z, a4.w)),
                   fmaxf(fmaxf(b4.x, b4.y), fmaxf(b4.z, b4.w)));
        a4 = *(float4*)&sred[(ly + 8) * 8];
        b4 = *(float4*)&sred[(ly + 8) * 8 + 4];
        m1 = fmaxf(fmaxf(fmaxf(a4.x, a4.y), fmaxf(a4.z, a4.w)),
                   fmaxf(fmaxf(b4.x, b4.y), fmaxf(b4.z, b4.w)));
    }

    float s0 = 0.f, s1 = 0.f;
#pragma unroll
    for (int j = 0; j < 16; j++) {
        acc[j][0] = fast_exp(acc[j][0] - m0);
        acc[j][1] = fast_exp(acc[j][1] - m0);
        acc[j][2] = fast_exp(acc[j][2] - m1);
        acc[j][3] = fast_exp(acc[j][3] - m1);
        s0 += acc[j][0] + acc[j][1];
        s1 += acc[j][2] + acc[j][3];
    }
    s0 += __shfl_xor_sync(0xffffffffu, s0, 1);
    s0 += __shfl_xor_sync(0xffffffffu, s0, 2);
    s1 += __shfl_xor_sync(0xffffffffu, s1, 1);
    s1 += __shfl_xor_sync(0xffffffffu, s1, 2);
    __syncthreads();   // everyone done reading maxes from sred
    if (lx == 0) {
        sred[ly * 8 + wid] = s0;
        sred[(ly + 8) * 8 + wid] = s1;
    }
    __syncthreads();
    float inv0, inv1;
    {
        float4 a4 = *(float4*)&sred[ly * 8];
        float4 b4 = *(float4*)&sred[ly * 8 + 4];
        inv0 = 1.f / (a4.x + a4.y + a4.z + a4.w + b4.x + b4.y + b4.z + b4.w);
        a4 = *(float4*)&sred[(ly + 8) * 8];
        b4 = *(float4*)&sred[(ly + 8) * 8 + 4];
        inv1 = 1.f / (a4.x + a4.y + a4.z + a4.w + b4.x + b4.y + b4.z + b4.w);
    }

    // ---- write probs + convert P to tf32 in registers ----
#pragma unroll
    for (int j = 0; j < 16; j++) {
        const int col = wn8 + 64 * j + 2 * lx;
        float p0 = acc[j][0] * inv0, p1 = acc[j][1] * inv0;
        float p2 = acc[j][2] * inv1, p3 = acc[j][3] * inv1;
        float2 v0 = {p0, p1};
        float2 v1 = {p2, p3};
        *(float2*)&probs[ly * 1024 + col] = v0;
        *(float2*)&probs[(ly + 8) * 1024 + col] = v1;
        acc[j][0] = __uint_as_float(f2tf(p0));
        acc[j][1] = __uint_as_float(f2tf(p1));
        acc[j][2] = __uint_as_float(f2tf(p2));
        acc[j][3] = __uint_as_float(f2tf(p3));
    }

    // ---- Phase 2: ctx = P @ V, k-split across warps via register P ----
    float pacc[8][4];
#pragma unroll
    for (int ni = 0; ni < 8; ni++)
#pragma unroll
        for (int q = 0; q < 4; q++) pacc[ni][q] = 0.f;

    uint32_t* Pme = Pw + wid * (QROWS * PWPITCH);
    const uint32_t* au = (const uint32_t*)acc;  // tf32 bits

#pragma unroll
    for (int vt = 0; vt < 8; vt++) {
        if (vt < 7) {
#pragma unroll
            for (int i = 0; i < 8; i++)
                CP_ASYNC16(smb + (((vt + 1) & 1) * KV_WORDS + (srow + i * 16) * VPITCH + sc4) * 4,
                           V + (size_t)(b * SEQ + (vt + 1) * 128 + srow + i * 16) * HID + h * DH + sc4);
            CP_COMMIT();
            CP_WAIT(1);
        } else {
            CP_WAIT(0);
        }
        __syncthreads();

        // patch this warp's two P col-groups into A-fragment layout
#pragma unroll
        for (int jj = 0; jj < 2; jj++) {
            const int j = 2 * vt + jj;
            uint2 t0 = {au[j * 4 + 0], au[j * 4 + 1]};
            uint2 t1 = {au[j * 4 + 2], au[j * 4 + 3]};
            *(uint2*)&Pme[ly * PWPITCH + jj * 8 + 2 * lx] = t0;
            *(uint2*)&Pme[(ly + 8) * PWPITCH + jj * 8 + 2 * lx] = t1;
        }
        __syncwarp();

        const uint32_t* VB = KVs + (vt & 1) * KV_WORDS;
#pragma unroll
        for (int jj = 0; jj < 2; jj++) {
            const int kb = jj * 8;
            uint32_t a[4];
            a[0] = Pme[ly * PWPITCH + kb + lx];
            a[1] = Pme[(ly + 8) * PWPITCH + kb + lx];
            a[2] = Pme[ly * PWPITCH + kb + lx + 4];
            a[3] = Pme[(ly + 8) * PWPITCH + kb + lx + 4];
            const int kl = jj * 64 + wn8;
#pragma unroll
            for (int ni = 0; ni < 8; ni++) {
                uint32_t bb[2];
                bb[0] = VB[(kl + lx) * VPITCH + ni * 8 + ly];
                bb[1] = VB[(kl + lx + 4) * VPITCH + ni * 8 + ly];
                mma_tf32(pacc[ni], a, bb);
            }
        }
        __syncthreads();
    }

    // ---- reduce partial ctx across the 8 warps (overlay on KV region) ----
#pragma unroll
    for (int ni = 0; ni < 8; ni++) {
        float2 v0 = {pacc[ni][0], pacc[ni][1]};
        float2 v1 = {pacc[ni][2], pacc[ni][3]};
        *(float2*)&red[wid * (QROWS * RED_PITCH) + ly * RED_PITCH + ni * 8 + 2 * lx] = v0;
        *(float2*)&red[wid * (QROWS * RED_PITCH) + (ly + 8) * RED_PITCH + ni * 8 + 2 * lx] = v1;
    }
    __syncthreads();

    {
        const int row = tid >> 4;            // 0..15
        const int col = (tid & 15) << 2;     // 0..60
        float s0v = 0.f, s1v = 0.f, s2v = 0.f, s3v = 0.f;
#pragma unroll
        for (int w = 0; w < 8; w++) {
            const float* rp = red + w * (QROWS * RED_PITCH) + row * RED_PITCH + col;
            s0v += rp[0]; s1v += rp[1]; s2v += rp[2]; s3v += rp[3];
        }
        float4 v = {s0v, s1v, s2v, s3v};
        *(float4*)(ctx + (size_t)(b * SEQ + qb * QROWS + row) * HID + h * DH + col) = v;
    }
}

// ---------------------------------------------------------------------------
extern "C" void kernel_launch(void* const* d_in, const int* in_sizes, int n_in,
                              void* d_out, int out_size) {
    (void)in_sizes; (void)n_in; (void)out_size;

    const float* m1 = (const float*)d_in[1];
    const float* m2 = (const float*)d_in[3];

    QKVArgs a;
    a.x[0] = (const float*)d_in[0];
    a.x[1] = (const float*)d_in[2];
    for (int i = 0; i < 6; i++) {
        a.w[i] = (const float*)d_in[4 + 2 * i];
        a.b[i] = (const float*)d_in[5 + 2 * i];
    }

    cudaFuncSetAttribute(qkv_gemm, cudaFuncAttributeMaxDynamicSharedMemorySize,
                         GEMM_SMEM);
    cudaFuncSetAttribute(attn_kernel, cudaFuncAttributeMaxDynamicSharedMemorySize,
                         ATTN_SMEM);

    qkv_gemm<<<dim3(16, 32, 6), 256, GEMM_SMEM>>>(a);
    attn_kernel<<<dim3(64, 16, 8), 256, ATTN_SMEM>>>(m1, m2, (float*)d_out);
}

// round 13
// speedup vs baseline: 1.5440x; 1.0319x over previous
#include <cuda_runtime.h>
#include <cstdint>

#define HID 1024
#define SEQ 1024
#define NB  4
#define NH  16
#define DH  64

// Scratch: q/k/v outputs (tf32-rounded) + tf32-preconverted inputs.
__device__ float g_qkv[6][NB * SEQ * HID];
__device__ float g_xc[2][NB * SEQ * HID];
__device__ float g_wc[6][HID * HID];

struct QKVArgs {
    const float* x[2];
    const float* w[6];
    const float* b[6];
};

__device__ __forceinline__ uint32_t f2tf(float x) {
    uint32_t t;
    asm("cvt.rna.tf32.f32 %0, %1;" : "=r"(t) : "f"(x));
    return t;
}

__device__ __forceinline__ void mma_tf32(float* c, const uint32_t* a, const uint32_t* b) {
    asm volatile(
        "mma.sync.aligned.m16n8k8.row.col.f32.tf32.tf32.f32 "
        "{%0,%1,%2,%3}, {%4,%5,%6,%7}, {%8,%9}, {%0,%1,%2,%3};\n"
        : "+f"(c[0]), "+f"(c[1]), "+f"(c[2]), "+f"(c[3])
        : "r"(a[0]), "r"(a[1]), "r"(a[2]), "r"(a[3]), "r"(b[0]), "r"(b[1]));
}

#define CP_ASYNC16(saddr, gptr) \
    asm volatile("cp.async.cg.shared.global [%0], [%1], 16;\n" :: "r"(saddr), "l"(gptr))
#define CP_COMMIT() asm volatile("cp.async.commit_group;\n" ::: "memory")
#define CP_WAIT(n)  asm volatile("cp.async.wait_group %0;\n" :: "n"(n) : "memory")

__device__ __forceinline__ float fast_exp(float x) {
    x = fmaxf(x, -80.f);
    float t = x * 1.44269504f;
    float r = rintf(t);
    float y = (t - r) * 0.69314718f;
    float p = 8.3333333e-3f;
    p = fmaf(p, y, 4.1666667e-2f);
    p = fmaf(p, y, 1.6666667e-1f);
    p = fmaf(p, y, 5.0e-1f);
    p = fmaf(p, y, 1.0f);
    p = fmaf(p, y, 1.0f);
    return __int_as_float(__float_as_int(p) + (((int)r) << 23));
}

// ---------------------------------------------------------------------------
// Pre-convert X (2x) and W (6x) to tf32 once.
// ---------------------------------------------------------------------------
__global__ __launch_bounds__(256) void conv_tf32(QKVArgs args) {
    const int seg = blockIdx.y;
    const float* src;
    float* dst;
    int n4;
    if (seg < 2) { src = args.x[seg]; dst = g_xc[seg]; n4 = NB * SEQ * HID / 4; }
    else         { src = args.w[seg - 2]; dst = g_wc[seg - 2]; n4 = HID * HID / 4; }
    const int stride = gridDim.x * blockDim.x;
    for (int i = blockIdx.x * blockDim.x + threadIdx.x; i < n4; i += stride) {
        float4 v = ((const float4*)src)[i];
        uint4 t = {f2tf(v.x), f2tf(v.y), f2tf(v.z), f2tf(v.w)};
        ((uint4*)dst)[i] = t;
    }
}

// ---------------------------------------------------------------------------
// QKV projection v2: 128x128x16 tile, 4-stage cp.async pipeline, 256 thr,
// warp tile 64x32, inputs pre-tf32 (pure byte staging). Bias added in fp32,
// result stored tf32-rounded.
// ---------------------------------------------------------------------------
#define STAGES  4
#define BK      16
#define APITCH  20
#define BPITCH  136
#define A_ST    (128 * APITCH)            // 2560 words
#define B_ST    (BK * BPITCH)             // 2176 words
#define ST_WORDS (A_ST + B_ST)            // 4736 words (18944 B, 16B-aligned)
#define GEMM_SMEM (STAGES * ST_WORDS * 4) // 75776 B

__global__ __launch_bounds__(256, 2) void qkv_gemm(QKVArgs args) {
    extern __shared__ uint32_t gsm[];

    const int p = blockIdx.z;
    const float* X    = g_xc[p / 3];
    const float* W    = g_wc[p];
    const float* bias = args.b[p];
    float* C = g_qkv[p];

    const int tid = threadIdx.x;
    const int wid = tid >> 5;
    const int lane = tid & 31;
    const int ly = lane >> 2;
    const int lx = lane & 3;
    const int wm = (wid & 1) * 64;
    const int wn = (wid >> 1) * 32;
    const int bm = blockIdx.y << 7;
    const int bn = blockIdx.x << 7;

    const uint32_t smb = (uint32_t)__cvta_generic_to_shared(gsm);

    // stage issue: A 128x16 (512 f4), B 16x128 (512 f4); 2+2 chunks/thread
    auto issue = [&](int s, int k0) {
        const uint32_t base = smb + s * (ST_WORDS * 4);
#pragma unroll
        for (int i = 0; i < 2; i++) {
            int c = tid + i * 256;
            int row = c >> 2, kc = (c & 3) << 2;
            CP_ASYNC16(base + (row * APITCH + kc) * 4,
                       X + (size_t)(bm + row) * HID + k0 + kc);
        }
#pragma unroll
        for (int i = 0; i < 2; i++) {
            int c = tid + i * 256;
            int kr = c >> 5, nc = (c & 31) << 2;
            CP_ASYNC16(base + (A_ST + kr * BPITCH + nc) * 4,
                       W + (size_t)(k0 + kr) * HID + bn + nc);
        }
        CP_COMMIT();
    };

    issue(0, 0);
    issue(1, BK);
    issue(2, 2 * BK);

    float acc[4][4][4];
#pragma unroll
    for (int i = 0; i < 4; i++)
#pragma unroll
        for (int j = 0; j < 4; j++)
#pragma unroll
            for (int q = 0; q < 4; q++) acc[i][j][q] = 0.f;

    const int NKT = HID / BK;   // 64
    for (int kt = 0; kt < NKT; kt++) {
        CP_WAIT(2);
        __syncthreads();
        if (kt + 3 < NKT) issue((kt + 3) & 3, (kt + 3) * BK);
        else CP_COMMIT();   // empty group keeps wait_group accounting exact

        const uint32_t* As = gsm + (kt & 3) * ST_WORDS;
        const uint32_t* Bs = As + A_ST;

#pragma unroll
        for (int ks = 0; ks < 2; ks++) {
            const int kk = ks * 8;
            uint32_t a[4][4], b[4][2];
#pragma unroll
            for (int mi = 0; mi < 4; mi++) {
                int m = wm + mi * 16;
                a[mi][0] = As[(m + ly) * APITCH + kk + lx];
                a[mi][1] = As[(m + ly + 8) * APITCH + kk + lx];
                a[mi][2] = As[(m + ly) * APITCH + kk + lx + 4];
                a[mi][3] = As[(m + ly + 8) * APITCH + kk + lx + 4];
            }
#pragma unroll
            for (int ni = 0; ni < 4; ni++) {
                int n = wn + ni * 8;
                b[ni][0] = Bs[(kk + lx) * BPITCH + n + ly];
                b[ni][1] = Bs[(kk + lx + 4) * BPITCH + n + ly];
            }
#pragma unroll
            for (int mi = 0; mi < 4; mi++)
#pragma unroll
                for (int ni = 0; ni < 4; ni++)
                    mma_tf32(acc[mi][ni], a[mi], b[ni]);
        }
    }

#pragma unroll
    for (int mi = 0; mi < 4; mi++) {
#pragma unroll
        for (int ni = 0; ni < 4; ni++) {
            int m = bm + wm + mi * 16 + ly;
            int n = bn + wn + ni * 8 + 2 * lx;
            float b0 = bias[n], b1 = bias[n + 1];
            float2 v0 = {__uint_as_float(f2tf(acc[mi][ni][0] + b0)),
                         __uint_as_float(f2tf(acc[mi][ni][1] + b1))};
            float2 v1 = {__uint_as_float(f2tf(acc[mi][ni][2] + b0)),
                         __uint_as_float(f2tf(acc[mi][ni][3] + b1))};
            *(float2*)(C + (size_t)m * HID + n) = v0;
            *(float2*)(C + (size_t)(m + 8) * HID + n) = v1;
        }
    }
}

// ---------------------------------------------------------------------------
// Fused cross-attention (unchanged from R12): register-resident scores,
// 16 q-rows/CTA, 256 thr, ~94KB smem -> 2 CTAs/SM.
// ---------------------------------------------------------------------------
#define QROWS   16
#define KPITCH  76
#define VPITCH  72
#define KV_WORDS (128 * KPITCH)
#define QPITCH  68
#define PWPITCH 18
#define RED_PITCH 68

#define SM_QS   (2 * KV_WORDS)
#define SM_MSK  (SM_QS + QROWS * QPITCH)
#define SM_SRED (SM_MSK + 1024)
#define SM_PW   (SM_SRED + 128)
#define ATTN_FLOATS (SM_PW + 8 * QROWS * PWPITCH)
#define ATTN_SMEM (ATTN_FLOATS * 4)

__global__ __launch_bounds__(256, 2) void attn_kernel(const float* __restrict__ mask1,
                                                      const float* __restrict__ mask2,
                                                      float* __restrict__ out) {
    extern __shared__ float sm[];
    uint32_t* KVs = (uint32_t*)sm;
    uint32_t* Qs  = (uint32_t*)(sm + SM_QS);
    float*    msk = sm + SM_MSK;
    float*    sred = sm + SM_SRED;
    uint32_t* Pw  = (uint32_t*)(sm + SM_PW);
    float*    red = sm;

    const int qb = blockIdx.x;
    const int h  = blockIdx.y;
    const int b  = blockIdx.z >> 1;
    const int st = blockIdx.z & 1;

    const float* Q    = g_qkv[st * 3];
    const float* K    = st ? g_qkv[1] : g_qkv[4];
    const float* V    = st ? g_qkv[2] : g_qkv[5];
    const float* mask = st ? mask1 : mask2;

    float* probs = out + 8388608 + (size_t)st * 67108864
                 + ((size_t)(b * NH + h) * SEQ + qb * QROWS) * SEQ;
    float* ctx = out + (size_t)st * 4194304;

    const int tid = threadIdx.x;
    const int wid = tid >> 5;
    const int lane = tid & 31;
    const int ly = lane >> 2;
    const int lx = lane & 3;
    const int wn8 = wid * 8;

    const int srow = tid >> 4;
    const int sc4 = (tid & 15) << 2;
    const uint32_t smb = (uint32_t)__cvta_generic_to_shared(sm);

    CP_ASYNC16(smb + (SM_MSK + tid * 4) * 4, mask + b * SEQ + tid * 4);
    CP_ASYNC16(smb + (SM_QS + srow * QPITCH + sc4) * 4,
               Q + (size_t)(b * SEQ + qb * QROWS + srow) * HID + h * DH + sc4);
#pragma unroll
    for (int i = 0; i < 8; i++)
        CP_ASYNC16(smb + ((srow + i * 16) * KPITCH + sc4) * 4,
                   K + (size_t)(b * SEQ + srow + i * 16) * HID + h * DH + sc4);
    CP_COMMIT();

    float acc[16][4];
#pragma unroll
    for (int j = 0; j < 16; j++)
#pragma unroll
        for (int q = 0; q < 4; q++) acc[j][q] = 0.f;

    uint32_t aq[8][4];

#pragma unroll
    for (int kt = 0; kt < 8; kt++) {
        if (kt < 7) {
#pragma unroll
            for (int i = 0; i < 8; i++)
                CP_ASYNC16(smb + (((kt + 1) & 1) * KV_WORDS + (srow + i * 16) * KPITCH + sc4) * 4,
                           K + (size_t)(b * SEQ + (kt + 1) * 128 + srow + i * 16) * HID + h * DH + sc4);
            CP_COMMIT();
            CP_WAIT(1);
        } else {
            CP_WAIT(0);
        }
        __syncthreads();

        if (kt == 0) {
#pragma unroll
            for (int ks = 0; ks < 8; ks++) {
                const int kk = ks * 8;
                aq[ks][0] = Qs[ly * QPITCH + kk + lx];
                aq[ks][1] = Qs[(ly + 8) * QPITCH + kk + lx];
                aq[ks][2] = Qs[ly * QPITCH + kk + lx + 4];
                aq[ks][3] = Qs[(ly + 8) * QPITCH + kk + lx + 4];
            }
        }

        const uint32_t* KB = KVs + (kt & 1) * KV_WORDS;
#pragma unroll
        for (int jj = 0; jj < 2; jj++) {
            const int nl = jj * 64 + wn8;
#pragma unroll
            for (int ks = 0; ks < 8; ks++) {
                const int kk = ks * 8;
                uint32_t bb[2];
                bb[0] = KB[(nl + ly) * KPITCH + kk + lx];
                bb[1] = KB[(nl + ly) * KPITCH + kk + lx + 4];
                mma_tf32(acc[2 * kt + jj], aq[ks], bb);
            }
        }
        __syncthreads();
    }

#pragma unroll
    for (int i = 0; i < 8; i++)
        CP_ASYNC16(smb + ((srow + i * 16) * VPITCH + sc4) * 4,
                   V + (size_t)(b * SEQ + srow + i * 16) * HID + h * DH + sc4);
    CP_COMMIT();

#pragma unroll
    for (int j = 0; j < 16; j++) {
        const int col = wn8 + 64 * j + 2 * lx;
        float mk0 = msk[col], mk1 = msk[col + 1];
        acc[j][0] = fmaf(acc[j][0], 0.125f, mk0);
        acc[j][1] = fmaf(acc[j][1], 0.125f, mk1);
        acc[j][2] = fmaf(acc[j][2], 0.125f, mk0);
        acc[j][3] = fmaf(acc[j][3], 0.125f, mk1);
    }

    float m0 = -1e30f, m1 = -1e30f;
#pragma unroll
    for (int j = 0; j < 16; j++) {
        m0 = fmaxf(m0, fmaxf(acc[j][0], acc[j][1]));
        m1 = fmaxf(m1, fmaxf(acc[j][2], acc[j][3]));
    }
    m0 = fmaxf(m0, __shfl_xor_sync(0xffffffffu, m0, 1));
    m0 = fmaxf(m0, __shfl_xor_sync(0xffffffffu, m0, 2));
    m1 = fmaxf(m1, __shfl_xor_sync(0xffffffffu, m1, 1));
    m1 = fmaxf(m1, __shfl_xor_sync(0xffffffffu, m1, 2));
    if (lx == 0) {
        sred[ly * 8 + wid] = m0;
        sred[(ly + 8) * 8 + wid] = m1;
    }
    __syncthreads();
    {
        float4 a4 = *(float4*)&sred[ly * 8];
        float4 b4 = *(float4*)&sred[ly * 8 + 4];
        m0 = fmaxf(fmaxf(fmaxf(a4.x, a4.y), fmaxf(a4.z, a4.w)),
                   fmaxf(fmaxf(b4.x, b4.y), fmaxf(b4.z, b4.w)));
        a4 = *(float4*)&sred[(ly + 8) * 8];
        b4 = *(float4*)&sred[(ly + 8) * 8 + 4];
        m1 = fmaxf(fmaxf(fmaxf(a4.x, a4.y), fmaxf(a4.z, a4.w)),
                   fmaxf(fmaxf(b4.x, b4.y), fmaxf(b4.z, b4.w)));
    }

    float s0 = 0.f, s1 = 0.f;
#pragma unroll
    for (int j = 0; j < 16; j++) {
        acc[j][0] = fast_exp(acc[j][0] - m0);
        acc[j][1] = fast_exp(acc[j][1] - m0);
        acc[j][2] = fast_exp(acc[j][2] - m1);
        acc[j][3] = fast_exp(acc[j][3] - m1);
        s0 += acc[j][0] + acc[j][1];
        s1 += acc[j][2] + acc[j][3];
    }
    s0 += __shfl_xor_sync(0xffffffffu, s0, 1);
    s0 += __shfl_xor_sync(0xffffffffu, s0, 2);
    s1 += __shfl_xor_sync(0xffffffffu, s1, 1);
    s1 += __shfl_xor_sync(0xffffffffu, s1, 2);
    __syncthreads();
    if (lx == 0) {
        sred[ly * 8 + wid] = s0;
        sred[(ly + 8) * 8 + wid] = s1;
    }
    __syncthreads();
    float inv0, inv1;
    {
        float4 a4 = *(float4*)&sred[ly * 8];
        float4 b4 = *(float4*)&sred[ly * 8 + 4];
        inv0 = 1.f / (a4.x + a4.y + a4.z + a4.w + b4.x + b4.y + b4.z + b4.w);
        a4 = *(float4*)&sred[(ly + 8) * 8];
        b4 = *(float4*)&sred[(ly + 8) * 8 + 4];
        inv1 = 1.f / (a4.x + a4.y + a4.z + a4.w + b4.x + b4.y + b4.z + b4.w);
    }

#pragma unroll
    for (int j = 0; j < 16; j++) {
        const int col = wn8 + 64 * j + 2 * lx;
        float p0 = acc[j][0] * inv0, p1 = acc[j][1] * inv0;
        float p2 = acc[j][2] * inv1, p3 = acc[j][3] * inv1;
        float2 v0 = {p0, p1};
        float2 v1 = {p2, p3};
        *(float2*)&probs[ly * 1024 + col] = v0;
        *(float2*)&probs[(ly + 8) * 1024 + col] = v1;
        acc[j][0] = __uint_as_float(f2tf(p0));
        acc[j][1] = __uint_as_float(f2tf(p1));
        acc[j][2] = __uint_as_float(f2tf(p2));
        acc[j][3] = __uint_as_float(f2tf(p3));
    }

    float pacc[8][4];
#pragma unroll
    for (int ni = 0; ni < 8; ni++)
#pragma unroll
        for (int q = 0; q < 4; q++) pacc[ni][q] = 0.f;

    uint32_t* Pme = Pw + wid * (QROWS * PWPITCH);
    const uint32_t* au = (const uint32_t*)acc;

#pragma unroll
    for (int vt = 0; vt < 8; vt++) {
        if (vt < 7) {
#pragma unroll
            for (int i = 0; i < 8; i++)
                CP_ASYNC16(smb + (((vt + 1) & 1) * KV_WORDS + (srow + i * 16) * VPITCH + sc4) * 4,
                           V + (size_t)(b * SEQ + (vt + 1) * 128 + srow + i * 16) * HID + h * DH + sc4);
            CP_COMMIT();
            CP_WAIT(1);
        } else {
            CP_WAIT(0);
        }
        __syncthreads();

#pragma unroll
        for (int jj = 0; jj < 2; jj++) {
            const int j = 2 * vt + jj;
            uint2 t0 = {au[j * 4 + 0], au[j * 4 + 1]};
            uint2 t1 = {au[j * 4 + 2], au[j * 4 + 3]};
            *(uint2*)&Pme[ly * PWPITCH + jj * 8 + 2 * lx] = t0;
            *(uint2*)&Pme[(ly + 8) * PWPITCH + jj * 8 + 2 * lx] = t1;
        }
        __syncwarp();

        const uint32_t* VB = KVs + (vt & 1) * KV_WORDS;
#pragma unroll
        for (int jj = 0; jj < 2; jj++) {
            const int kb = jj * 8;
            uint32_t a[4];
            a[0] = Pme[ly * PWPITCH + kb + lx];
            a[1] = Pme[(ly + 8) * PWPITCH + kb + lx];
            a[2] = Pme[ly * PWPITCH + kb + lx + 4];
            a[3] = Pme[(ly + 8) * PWPITCH + kb + lx + 4];
            const int kl = jj * 64 + wn8;
#pragma unroll
            for (int ni = 0; ni < 8; ni++) {
                uint32_t bb[2];
                bb[0] = VB[(kl + lx) * VPITCH + ni * 8 + ly];
                bb[1] = VB[(kl + lx + 4) * VPITCH + ni * 8 + ly];
                mma_tf32(pacc[ni], a, bb);
            }
        }
        __syncthreads();
    }

#pragma unroll
    for (int ni = 0; ni < 8; ni++) {
        float2 v0 = {pacc[ni][0], pacc[ni][1]};
        float2 v1 = {pacc[ni][2], pacc[ni][3]};
        *(float2*)&red[wid * (QROWS * RED_PITCH) + ly * RED_PITCH + ni * 8 + 2 * lx] = v0;
        *(float2*)&red[wid * (QROWS * RED_PITCH) + (ly + 8) * RED_PITCH + ni * 8 + 2 * lx] = v1;
    }
    __syncthreads();

    {
        const int row = tid >> 4;
        const int col = (tid & 15) << 2;
        float s0v = 0.f, s1v = 0.f, s2v = 0.f, s3v = 0.f;
#pragma unroll
        for (int w = 0; w < 8; w++) {
            const float* rp = red + w * (QROWS * RED_PITCH) + row * RED_PITCH + col;
            s0v += rp[0]; s1v += rp[1]; s2v += rp[2]; s3v += rp[3];
        }
        float4 v = {s0v, s1v, s2v, s3v};
        *(float4*)(ctx + (size_t)(b * SEQ + qb * QROWS + row) * HID + h * DH + col) = v;
    }
}

// ---------------------------------------------------------------------------
extern "C" void kernel_launch(void* const* d_in, const int* in_sizes, int n_in,
                              void* d_out, int out_size) {
    (void)in_sizes; (void)n_in; (void)out_size;

    const float* m1 = (const float*)d_in[1];
    const float* m2 = (const float*)d_in[3];

    QKVArgs a;
    a.x[0] = (const float*)d_in[0];
    a.x[1] = (const float*)d_in[2];
    for (int i = 0; i < 6; i++) {
        a.w[i] = (const float*)d_in[4 + 2 * i];
        a.b[i] = (const float*)d_in[5 + 2 * i];
    }

    cudaFuncSetAttribute(qkv_gemm, cudaFuncAttributeMaxDynamicSharedMemorySize,
                         GEMM_SMEM);
    cudaFuncSetAttribute(attn_kernel, cudaFuncAttributeMaxDynamicSharedMemorySize,
                         ATTN_SMEM);

    conv_tf32<<<dim3(1024, 8), 256>>>(a);
    qkv_gemm<<<dim3(8, 32, 6), 256, GEMM_SMEM>>>(a);
    attn_kernel<<<dim3(64, 16, 8), 256, ATTN_SMEM>>>(m1, m2, (float*)d_out);
}

// round 14
// speedup vs baseline: 1.5479x; 1.0025x over previous
#include <cuda_runtime.h>
#include <cstdint>

#define HID 1024
#define SEQ 1024
#define NB  4
#define NH  16
#define DH  64

// Scratch: q/k/v outputs (tf32-rounded) + tf32-preconverted inputs.
__device__ float g_qkv[6][NB * SEQ * HID];
__device__ float g_xc[2][NB * SEQ * HID];
__device__ float g_wc[6][HID * HID];

struct QKVArgs {
    const float* x[2];
    const float* w[6];
    const float* b[6];
};

__device__ __forceinline__ uint32_t f2tf(float x) {
    uint32_t t;
    asm("cvt.rna.tf32.f32 %0, %1;" : "=r"(t) : "f"(x));
    return t;
}

__device__ __forceinline__ void mma_tf32(float* c, const uint32_t* a, const uint32_t* b) {
    asm volatile(
        "mma.sync.aligned.m16n8k8.row.col.f32.tf32.tf32.f32 "
        "{%0,%1,%2,%3}, {%4,%5,%6,%7}, {%8,%9}, {%0,%1,%2,%3};\n"
        : "+f"(c[0]), "+f"(c[1]), "+f"(c[2]), "+f"(c[3])
        : "r"(a[0]), "r"(a[1]), "r"(a[2]), "r"(a[3]), "r"(b[0]), "r"(b[1]));
}

#define CP_ASYNC16(saddr, gptr) \
    asm volatile("cp.async.cg.shared.global [%0], [%1], 16;\n" :: "r"(saddr), "l"(gptr))
#define CP_COMMIT() asm volatile("cp.async.commit_group;\n" ::: "memory")
#define CP_WAIT(n)  asm volatile("cp.async.wait_group %0;\n" :: "n"(n) : "memory")

__device__ __forceinline__ float fast_exp(float x) {
    x = fmaxf(x, -80.f);
    float t = x * 1.44269504f;
    float r = rintf(t);
    float y = (t - r) * 0.69314718f;
    float p = 8.3333333e-3f;
    p = fmaf(p, y, 4.1666667e-2f);
    p = fmaf(p, y, 1.6666667e-1f);
    p = fmaf(p, y, 5.0e-1f);
    p = fmaf(p, y, 1.0f);
    p = fmaf(p, y, 1.0f);
    return __int_as_float(__float_as_int(p) + (((int)r) << 23));
}

// ---------------------------------------------------------------------------
// Pre-convert X (2x) and W (6x) to tf32 once. (unchanged from R13)
// ---------------------------------------------------------------------------
__global__ __launch_bounds__(256) void conv_tf32(QKVArgs args) {
    const int seg = blockIdx.y;
    const float* src;
    float* dst;
    int n4;
    if (seg < 2) { src = args.x[seg]; dst = g_xc[seg]; n4 = NB * SEQ * HID / 4; }
    else         { src = args.w[seg - 2]; dst = g_wc[seg - 2]; n4 = HID * HID / 4; }
    const int stride = gridDim.x * blockDim.x;
    for (int i = blockIdx.x * blockDim.x + threadIdx.x; i < n4; i += stride) {
        float4 v = ((const float4*)src)[i];
        uint4 t = {f2tf(v.x), f2tf(v.y), f2tf(v.z), f2tf(v.w)};
        ((uint4*)dst)[i] = t;
    }
}

// ---------------------------------------------------------------------------
// QKV projection: 128x128x16, 4-stage cp.async pipeline. (unchanged from R13)
// ---------------------------------------------------------------------------
#define STAGES  4
#define BK      16
#define APITCH  20
#define BPITCH  136
#define A_ST    (128 * APITCH)
#define B_ST    (BK * BPITCH)
#define ST_WORDS (A_ST + B_ST)
#define GEMM_SMEM (STAGES * ST_WORDS * 4)

__global__ __launch_bounds__(256, 2) void qkv_gemm(QKVArgs args) {
    extern __shared__ uint32_t gsm[];

    const int p = blockIdx.z;
    const float* X    = g_xc[p / 3];
    const float* W    = g_wc[p];
    const float* bias = args.b[p];
    float* C = g_qkv[p];

    const int tid = threadIdx.x;
    const int wid = tid >> 5;
    const int lane = tid & 31;
    const int ly = lane >> 2;
    const int lx = lane & 3;
    const int wm = (wid & 1) * 64;
    const int wn = (wid >> 1) * 32;
    const int bm = blockIdx.y << 7;
    const int bn = blockIdx.x << 7;

    const uint32_t smb = (uint32_t)__cvta_generic_to_shared(gsm);

    auto issue = [&](int s, int k0) {
        const uint32_t base = smb + s * (ST_WORDS * 4);
#pragma unroll
        for (int i = 0; i < 2; i++) {
            int c = tid + i * 256;
            int row = c >> 2, kc = (c & 3) << 2;
            CP_ASYNC16(base + (row * APITCH + kc) * 4,
                       X + (size_t)(bm + row) * HID + k0 + kc);
        }
#pragma unroll
        for (int i = 0; i < 2; i++) {
            int c = tid + i * 256;
            int kr = c >> 5, nc = (c & 31) << 2;
            CP_ASYNC16(base + (A_ST + kr * BPITCH + nc) * 4,
                       W + (size_t)(k0 + kr) * HID + bn + nc);
        }
        CP_COMMIT();
    };

    issue(0, 0);
    issue(1, BK);
    issue(2, 2 * BK);

    float acc[4][4][4];
#pragma unroll
    for (int i = 0; i < 4; i++)
#pragma unroll
        for (int j = 0; j < 4; j++)
#pragma unroll
            for (int q = 0; q < 4; q++) acc[i][j][q] = 0.f;

    const int NKT = HID / BK;
    for (int kt = 0; kt < NKT; kt++) {
        CP_WAIT(2);
        __syncthreads();
        if (kt + 3 < NKT) issue((kt + 3) & 3, (kt + 3) * BK);
        else CP_COMMIT();

        const uint32_t* As = gsm + (kt & 3) * ST_WORDS;
        const uint32_t* Bs = As + A_ST;

#pragma unroll
        for (int ks = 0; ks < 2; ks++) {
            const int kk = ks * 8;
            uint32_t a[4][4], b[4][2];
#pragma unroll
            for (int mi = 0; mi < 4; mi++) {
                int m = wm + mi * 16;
                a[mi][0] = As[(m + ly) * APITCH + kk + lx];
                a[mi][1] = As[(m + ly + 8) * APITCH + kk + lx];
                a[mi][2] = As[(m + ly) * APITCH + kk + lx + 4];
                a[mi][3] = As[(m + ly + 8) * APITCH + kk + lx + 4];
            }
#pragma unroll
            for (int ni = 0; ni < 4; ni++) {
                int n = wn + ni * 8;
                b[ni][0] = Bs[(kk + lx) * BPITCH + n + ly];
                b[ni][1] = Bs[(kk + lx + 4) * BPITCH + n + ly];
            }
#pragma unroll
            for (int mi = 0; mi < 4; mi++)
#pragma unroll
                for (int ni = 0; ni < 4; ni++)
                    mma_tf32(acc[mi][ni], a[mi], b[ni]);
        }
    }

#pragma unroll
    for (int mi = 0; mi < 4; mi++) {
#pragma unroll
        for (int ni = 0; ni < 4; ni++) {
            int m = bm + wm + mi * 16 + ly;
            int n = bn + wn + ni * 8 + 2 * lx;
            float b0 = bias[n], b1 = bias[n + 1];
            float2 v0 = {__uint_as_float(f2tf(acc[mi][ni][0] + b0)),
                         __uint_as_float(f2tf(acc[mi][ni][1] + b1))};
            float2 v1 = {__uint_as_float(f2tf(acc[mi][ni][2] + b0)),
                         __uint_as_float(f2tf(acc[mi][ni][3] + b1))};
            *(float2*)(C + (size_t)m * HID + n) = v0;
            *(float2*)(C + (size_t)(m + 8) * HID + n) = v1;
        }
    }
}

// ---------------------------------------------------------------------------
// Fused cross-attention v3: register-resident scores + WARP-PRIVATE K/V
// staging (warp w only ever touches rows kt*128 + jj*64 + w*8 + {0..7}).
// No CTA barriers in either mainloop. 16 q-rows/CTA, 256 thr, 94KB smem.
// ---------------------------------------------------------------------------
#define QROWS   16
#define WPITCH  76
#define WBUF    (16 * WPITCH)        // words per buffer per warp
#define WREGION (2 * WBUF)           // double buffer per warp
#define KVW_WORDS (8 * WREGION)
#define QPITCH  68
#define PWPITCH 18
#define RED_PITCH 68

#define SM_QS   KVW_WORDS
#define SM_MSK  (SM_QS + QROWS * QPITCH)
#define SM_SRED (SM_MSK + 1024)
#define SM_PW   (SM_SRED + 128)
#define ATTN_FLOATS (SM_PW + 8 * QROWS * PWPITCH)
#define ATTN_SMEM (ATTN_FLOATS * 4)

__global__ __launch_bounds__(256, 2) void attn_kernel(const float* __restrict__ mask1,
                                                      const float* __restrict__ mask2,
                                                      float* __restrict__ out) {
    extern __shared__ float sm[];
    uint32_t* KVW = (uint32_t*)sm;             // 8 x 2 x [16][WPITCH]
    uint32_t* Qs  = (uint32_t*)(sm + SM_QS);   // [16][QPITCH]
    float*    msk = sm + SM_MSK;               // [1024]
    float*    sred = sm + SM_SRED;             // [16][8]
    uint32_t* Pw  = (uint32_t*)(sm + SM_PW);   // 8 x [16][PWPITCH]

    const int qb = blockIdx.x;
    const int h  = blockIdx.y;
    const int b  = blockIdx.z >> 1;
    const int st = blockIdx.z & 1;

    const float* Q    = g_qkv[st * 3];
    const float* K    = st ? g_qkv[1] : g_qkv[4];
    const float* V    = st ? g_qkv[2] : g_qkv[5];
    const float* mask = st ? mask1 : mask2;

    float* probs = out + 8388608 + (size_t)st * 67108864
                 + ((size_t)(b * NH + h) * SEQ + qb * QROWS) * SEQ;
    float* ctx = out + (size_t)st * 4194304;

    const int tid = threadIdx.x;
    const int wid = tid >> 5;
    const int lane = tid & 31;
    const int ly = lane >> 2;
    const int lx = lane & 3;
    const int wn8 = wid * 8;

    const int srow = tid >> 4;
    const int sc4 = (tid & 15) << 2;
    const uint32_t smb = (uint32_t)__cvta_generic_to_shared(sm);

    // per-warp staging of this warp's 16 rows of a 128-row tile
    auto stage = [&](const float* src, int tile, int buf) {
        const uint32_t base = smb + (wid * WREGION + buf * WBUF) * 4;
#pragma unroll
        for (int i = 0; i < 8; i++) {
            int idx = lane + 32 * i;
            int r = idx >> 4, c4 = (idx & 15) << 2;
            int grow = tile * 128 + ((r >> 3) << 6) + wn8 + (r & 7);
            CP_ASYNC16(base + (r * WPITCH + c4) * 4,
                       src + (size_t)(b * SEQ + grow) * HID + h * DH + c4);
        }
        CP_COMMIT();
    };

    // G0: mask + Q (CTA-wide)
    CP_ASYNC16(smb + (SM_MSK + tid * 4) * 4, mask + b * SEQ + tid * 4);
    CP_ASYNC16(smb + (SM_QS + srow * QPITCH + sc4) * 4,
               Q + (size_t)(b * SEQ + qb * QROWS + srow) * HID + h * DH + sc4);
    CP_COMMIT();
    // G1: this warp's K tile 0
    stage(K, 0, 0);

    CP_WAIT(1);          // G0 done (G1 may be in flight)
    __syncthreads();     // mask + Q visible CTA-wide

    uint32_t aq[8][4];
#pragma unroll
    for (int ks = 0; ks < 8; ks++) {
        const int kk = ks * 8;
        aq[ks][0] = Qs[ly * QPITCH + kk + lx];
        aq[ks][1] = Qs[(ly + 8) * QPITCH + kk + lx];
        aq[ks][2] = Qs[ly * QPITCH + kk + lx + 4];
        aq[ks][3] = Qs[(ly + 8) * QPITCH + kk + lx + 4];
    }

    float acc[16][4];
#pragma unroll
    for (int j = 0; j < 16; j++)
#pragma unroll
        for (int q = 0; q < 4; q++) acc[j][q] = 0.f;

    // ---- Phase 1: warp-private, barrier-free ----
#pragma unroll
    for (int kt = 0; kt < 8; kt++) {
        if (kt < 7) { stage(K, kt + 1, (kt + 1) & 1); CP_WAIT(1); }
        else CP_WAIT(0);

        const uint32_t* KB = KVW + wid * WREGION + (kt & 1) * WBUF;
#pragma unroll
        for (int jj = 0; jj < 2; jj++) {
#pragma unroll
            for (int ks = 0; ks < 8; ks++) {
                const int kk = ks * 8;
                uint32_t bb[2];
                bb[0] = KB[(jj * 8 + ly) * WPITCH + kk + lx];
                bb[1] = KB[(jj * 8 + ly) * WPITCH + kk + lx + 4];
                mma_tf32(acc[2 * kt + jj], aq[ks], bb);
            }
        }
    }

    // prefetch this warp's V tile 0 (overlaps softmax)
    stage(V, 0, 0);

    // ---- scale + mask ----
#pragma unroll
    for (int j = 0; j < 16; j++) {
        const int col = wn8 + 64 * j + 2 * lx;
        float mk0 = msk[col], mk1 = msk[col + 1];
        acc[j][0] = fmaf(acc[j][0], 0.125f, mk0);
        acc[j][1] = fmaf(acc[j][1], 0.125f, mk1);
        acc[j][2] = fmaf(acc[j][2], 0.125f, mk0);
        acc[j][3] = fmaf(acc[j][3], 0.125f, mk1);
    }

    // ---- softmax on registers + tiny cross-warp reduce ----
    float m0 = -1e30f, m1 = -1e30f;
#pragma unroll
    for (int j = 0; j < 16; j++) {
        m0 = fmaxf(m0, fmaxf(acc[j][0], acc[j][1]));
        m1 = fmaxf(m1, fmaxf(acc[j][2], acc[j][3]));
    }
    m0 = fmaxf(m0, __shfl_xor_sync(0xffffffffu, m0, 1));
    m0 = fmaxf(m0, __shfl_xor_sync(0xffffffffu, m0, 2));
    m1 = fmaxf(m1, __shfl_xor_sync(0xffffffffu, m1, 1));
    m1 = fmaxf(m1, __shfl_xor_sync(0xffffffffu, m1, 2));
    if (lx == 0) {
        sred[ly * 8 + wid] = m0;
        sred[(ly + 8) * 8 + wid] = m1;
    }
    __syncthreads();
    {
        float4 a4 = *(float4*)&sred[ly * 8];
        float4 b4 = *(float4*)&sred[ly * 8 + 4];
        m0 = fmaxf(fmaxf(fmaxf(a4.x, a4.y), fmaxf(a4.z, a4.w)),
                   fmaxf(fmaxf(b4.x, b4.y), fmaxf(b4.z, b4.w)));
        a4 = *(float4*)&sred[(ly + 8) * 8];
        b4 = *(float4*)&sred[(ly + 8) * 8 + 4];
        m1 = fmaxf(fmaxf(fmaxf(a4.x, a4.y), fmaxf(a4.z, a4.w)),
                   fmaxf(fmaxf(b4.x, b4.y), fmaxf(b4.z, b4.w)));
    }

    float s0 = 0.f, s1 = 0.f;
#pragma unroll
    for (int j = 0; j < 16; j++) {
        acc[j][0] = fast_exp(acc[j][0] - m0);
        acc[j][1] = fast_exp(acc[j][1] - m0);
        acc[j][2] = fast_exp(acc[j][2] - m1);
        acc[j][3] = fast_exp(acc[j][3] - m1);
        s0 += acc[j][0] + acc[j][1];
        s1 += acc[j][2] + acc[j][3];
    }
    s0 += __shfl_xor_sync(0xffffffffu, s0, 1);
    s0 += __shfl_xor_sync(0xffffffffu, s0, 2);
    s1 += __shfl_xor_sync(0xffffffffu, s1, 1);
    s1 += __shfl_xor_sync(0xffffffffu, s1, 2);
    __syncthreads();
    if (lx == 0) {
        sred[ly * 8 + wid] = s0;
        sred[(ly + 8) * 8 + wid] = s1;
    }
    __syncthreads();
    float inv0, inv1;
    {
        float4 a4 = *(float4*)&sred[ly * 8];
        float4 b4 = *(float4*)&sred[ly * 8 + 4];
        inv0 = 1.f / (a4.x + a4.y + a4.z + a4.w + b4.x + b4.y + b4.z + b4.w);
        a4 = *(float4*)&sred[(ly + 8) * 8];
        b4 = *(float4*)&sred[(ly + 8) * 8 + 4];
        inv1 = 1.f / (a4.x + a4.y + a4.z + a4.w + b4.x + b4.y + b4.z + b4.w);
    }

    // ---- write probs + convert P to tf32 in registers ----
#pragma unroll
    for (int j = 0; j < 16; j++) {
        const int col = wn8 + 64 * j + 2 * lx;
        float p0 = acc[j][0] * inv0, p1 = acc[j][1] * inv0;
        float p2 = acc[j][2] * inv1, p3 = acc[j][3] * inv1;
        float2 v0 = {p0, p1};
        float2 v1 = {p2, p3};
        *(float2*)&probs[ly * 1024 + col] = v0;
        *(float2*)&probs[(ly + 8) * 1024 + col] = v1;
        acc[j][0] = __uint_as_float(f2tf(p0));
        acc[j][1] = __uint_as_float(f2tf(p1));
        acc[j][2] = __uint_as_float(f2tf(p2));
        acc[j][3] = __uint_as_float(f2tf(p3));
    }

    // ---- Phase 2: warp-private, barrier-free ----
    float pacc[8][4];
#pragma unroll
    for (int ni = 0; ni < 8; ni++)
#pragma unroll
        for (int q = 0; q < 4; q++) pacc[ni][q] = 0.f;

    uint32_t* Pme = Pw + wid * (QROWS * PWPITCH);
    const uint32_t* au = (const uint32_t*)acc;

#pragma unroll
    for (int vt = 0; vt < 8; vt++) {
        if (vt < 7) { stage(V, vt + 1, (vt + 1) & 1); CP_WAIT(1); }
        else CP_WAIT(0);

        // patch this warp's two P col-groups into A-fragment layout
#pragma unroll
        for (int jj = 0; jj < 2; jj++) {
            const int j = 2 * vt + jj;
            uint2 t0 = {au[j * 4 + 0], au[j * 4 + 1]};
            uint2 t1 = {au[j * 4 + 2], au[j * 4 + 3]};
            *(uint2*)&Pme[ly * PWPITCH + jj * 8 + 2 * lx] = t0;
            *(uint2*)&Pme[(ly + 8) * PWPITCH + jj * 8 + 2 * lx] = t1;
        }
        __syncwarp();

        const uint32_t* VB = KVW + wid * WREGION + (vt & 1) * WBUF;
#pragma unroll
        for (int jj = 0; jj < 2; jj++) {
            const int kb = jj * 8;
            uint32_t a[4];
            a[0] = Pme[ly * PWPITCH + kb + lx];
            a[1] = Pme[(ly + 8) * PWPITCH + kb + lx];
            a[2] = Pme[ly * PWPITCH + kb + lx + 4];
            a[3] = Pme[(ly + 8) * PWPITCH + kb + lx + 4];
#pragma unroll
            for (int ni = 0; ni < 8; ni++) {
                uint32_t bb[2];
                bb[0] = VB[(jj * 8 + lx) * WPITCH + ni * 8 + ly];
                bb[1] = VB[(jj * 8 + lx + 4) * WPITCH + ni * 8 + ly];
                mma_tf32(pacc[ni], a, bb);
            }
        }
        __syncwarp();   // Pme reads done before next iteration's patch
    }

    // ---- ctx reduce: each warp writes partials into ITS OWN KV region ----
    {
        float* red_w = sm + wid * WREGION;   // own region: no cross-warp hazard
#pragma unroll
        for (int ni = 0; ni < 8; ni++) {
            float2 v0 = {pacc[ni][0], pacc[ni][1]};
            float2 v1 = {pacc[ni][2], pacc[ni][3]};
            *(float2*)&red_w[ly * RED_PITCH + ni * 8 + 2 * lx] = v0;
            *(float2*)&red_w[(ly + 8) * RED_PITCH + ni * 8 + 2 * lx] = v1;
        }
    }
    __syncthreads();

    {
        const int row = tid >> 4;
        const int col = (tid & 15) << 2;
        float s0v = 0.f, s1v = 0.f, s2v = 0.f, s3v = 0.f;
#pragma unroll
        for (int w = 0; w < 8; w++) {
            const float* rp = sm + w * WREGION + row * RED_PITCH + col;
            s0v += rp[0]; s1v += rp[1]; s2v += rp[2]; s3v += rp[3];
        }
        float4 v = {s0v, s1v, s2v, s3v};
        *(float4*)(ctx + (size_t)(b * SEQ + qb * QROWS + row) * HID + h * DH + col) = v;
    }
}

// ---------------------------------------------------------------------------
extern "C" void kernel_launch(void* const* d_in, const int* in_sizes, int n_in,
                              void* d_out, int out_size) {
    (void)in_sizes; (void)n_in; (void)out_size;

    const float* m1 = (const float*)d_in[1];
    const float* m2 = (const float*)d_in[3];

    QKVArgs a;
    a.x[0] = (const float*)d_in[0];
    a.x[1] = (const float*)d_in[2];
    for (int i = 0; i < 6; i++) {
        a.w[i] = (const float*)d_in[4 + 2 * i];
        a.b[i] = (const float*)d_in[5 + 2 * i];
    }

    cudaFuncSetAttribute(qkv_gemm, cudaFuncAttributeMaxDynamicSharedMemorySize,
                         GEMM_SMEM);
    cudaFuncSetAttribute(attn_kernel, cudaFuncAttributeMaxDynamicSharedMemorySize,
                         ATTN_SMEM);

    conv_tf32<<<dim3(1024, 8), 256>>>(a);
    qkv_gemm<<<dim3(8, 32, 6), 256, GEMM_SMEM>>>(a);
    attn_kernel<<<dim3(64, 16, 8), 256, ATTN_SMEM>>>(m1, m2, (float*)d_out);
}

// round 15
// speedup vs baseline: 1.6797x; 1.0851x over previous
#include <cuda_runtime.h>
#include <cstdint>

#define HID 1024
#define SEQ 1024
#define NB  4
#define NH  16
#define DH  64

// Scratch: q/k/v outputs (tf32-rounded) + tf32-preconverted inputs.
__device__ float g_qkv[6][NB * SEQ * HID];
__device__ float g_xc[2][NB * SEQ * HID];
__device__ float g_wc[6][HID * HID];

struct QKVArgs {
    const float* x[2];
    const float* w[6];
    const float* b[6];
};

__device__ __forceinline__ uint32_t f2tf(float x) {
    uint32_t t;
    asm("cvt.rna.tf32.f32 %0, %1;" : "=r"(t) : "f"(x));
    return t;
}

__device__ __forceinline__ void mma_tf32(float* c, const uint32_t* a, const uint32_t* b) {
    asm volatile(
        "mma.sync.aligned.m16n8k8.row.col.f32.tf32.tf32.f32 "
        "{%0,%1,%2,%3}, {%4,%5,%6,%7}, {%8,%9}, {%0,%1,%2,%3};\n"
        : "+f"(c[0]), "+f"(c[1]), "+f"(c[2]), "+f"(c[3])
        : "r"(a[0]), "r"(a[1]), "r"(a[2]), "r"(a[3]), "r"(b[0]), "r"(b[1]));
}

#define CP_ASYNC16(saddr, gptr) \
    asm volatile("cp.async.cg.shared.global [%0], [%1], 16;\n" :: "r"(saddr), "l"(gptr))
#define CP_COMMIT() asm volatile("cp.async.commit_group;\n" ::: "memory")
#define CP_WAIT(n)  asm volatile("cp.async.wait_group %0;\n" :: "n"(n) : "memory")

__device__ __forceinline__ float fast_exp(float x) {
    x = fmaxf(x, -80.f);
    float t = x * 1.44269504f;
    float r = rintf(t);
    float y = (t - r) * 0.69314718f;
    float p = 8.3333333e-3f;
    p = fmaf(p, y, 4.1666667e-2f);
    p = fmaf(p, y, 1.6666667e-1f);
    p = fmaf(p, y, 5.0e-1f);
    p = fmaf(p, y, 1.0f);
    p = fmaf(p, y, 1.0f);
    return __int_as_float(__float_as_int(p) + (((int)r) << 23));
}

// ---------------------------------------------------------------------------
// Pre-convert X (2x) and W (6x) to tf32 once. (unchanged)
// ---------------------------------------------------------------------------
__global__ __launch_bounds__(256) void conv_tf32(QKVArgs args) {
    const int seg = blockIdx.y;
    const float* src;
    float* dst;
    int n4;
    if (seg < 2) { src = args.x[seg]; dst = g_xc[seg]; n4 = NB * SEQ * HID / 4; }
    else         { src = args.w[seg - 2]; dst = g_wc[seg - 2]; n4 = HID * HID / 4; }
    const int stride = gridDim.x * blockDim.x;
    for (int i = blockIdx.x * blockDim.x + threadIdx.x; i < n4; i += stride) {
        float4 v = ((const float4*)src)[i];
        uint4 t = {f2tf(v.x), f2tf(v.y), f2tf(v.z), f2tf(v.w)};
        ((uint4*)dst)[i] = t;
    }
}

// ---------------------------------------------------------------------------
// QKV projection: 128x128x16, 4-stage cp.async pipeline. (unchanged)
// ---------------------------------------------------------------------------
#define STAGES  4
#define BK      16
#define APITCH  20
#define BPITCH  136
#define A_ST    (128 * APITCH)
#define B_ST    (BK * BPITCH)
#define ST_WORDS (A_ST + B_ST)
#define GEMM_SMEM (STAGES * ST_WORDS * 4)

__global__ __launch_bounds__(256, 2) void qkv_gemm(QKVArgs args) {
    extern __shared__ uint32_t gsm[];

    const int p = blockIdx.z;
    const float* X    = g_xc[p / 3];
    const float* W    = g_wc[p];
    const float* bias = args.b[p];
    float* C = g_qkv[p];

    const int tid = threadIdx.x;
    const int wid = tid >> 5;
    const int lane = tid & 31;
    const int ly = lane >> 2;
    const int lx = lane & 3;
    const int wm = (wid & 1) * 64;
    const int wn = (wid >> 1) * 32;
    const int bm = blockIdx.y << 7;
    const int bn = blockIdx.x << 7;

    const uint32_t smb = (uint32_t)__cvta_generic_to_shared(gsm);

    auto issue = [&](int s, int k0) {
        const uint32_t base = smb + s * (ST_WORDS * 4);
#pragma unroll
        for (int i = 0; i < 2; i++) {
            int c = tid + i * 256;
            int row = c >> 2, kc = (c & 3) << 2;
            CP_ASYNC16(base + (row * APITCH + kc) * 4,
                       X + (size_t)(bm + row) * HID + k0 + kc);
        }
#pragma unroll
        for (int i = 0; i < 2; i++) {
            int c = tid + i * 256;
            int kr = c >> 5, nc = (c & 31) << 2;
            CP_ASYNC16(base + (A_ST + kr * BPITCH + nc) * 4,
                       W + (size_t)(k0 + kr) * HID + bn + nc);
        }
        CP_COMMIT();
    };

    issue(0, 0);
    issue(1, BK);
    issue(2, 2 * BK);

    float acc[4][4][4];
#pragma unroll
    for (int i = 0; i < 4; i++)
#pragma unroll
        for (int j = 0; j < 4; j++)
#pragma unroll
            for (int q = 0; q < 4; q++) acc[i][j][q] = 0.f;

    const int NKT = HID / BK;
    for (int kt = 0; kt < NKT; kt++) {
        CP_WAIT(2);
        __syncthreads();
        if (kt + 3 < NKT) issue((kt + 3) & 3, (kt + 3) * BK);
        else CP_COMMIT();

        const uint32_t* As = gsm + (kt & 3) * ST_WORDS;
        const uint32_t* Bs = As + A_ST;

#pragma unroll
        for (int ks = 0; ks < 2; ks++) {
            const int kk = ks * 8;
            uint32_t a[4][4], b[4][2];
#pragma unroll
            for (int mi = 0; mi < 4; mi++) {
                int m = wm + mi * 16;
                a[mi][0] = As[(m + ly) * APITCH + kk + lx];
                a[mi][1] = As[(m + ly + 8) * APITCH + kk + lx];
                a[mi][2] = As[(m + ly) * APITCH + kk + lx + 4];
                a[mi][3] = As[(m + ly + 8) * APITCH + kk + lx + 4];
            }
#pragma unroll
            for (int ni = 0; ni < 4; ni++) {
                int n = wn + ni * 8;
                b[ni][0] = Bs[(kk + lx) * BPITCH + n + ly];
                b[ni][1] = Bs[(kk + lx + 4) * BPITCH + n + ly];
            }
#pragma unroll
            for (int mi = 0; mi < 4; mi++)
#pragma unroll
                for (int ni = 0; ni < 4; ni++)
                    mma_tf32(acc[mi][ni], a[mi], b[ni]);
        }
    }

#pragma unroll
    for (int mi = 0; mi < 4; mi++) {
#pragma unroll
        for (int ni = 0; ni < 4; ni++) {
            int m = bm + wm + mi * 16 + ly;
            int n = bn + wn + ni * 8 + 2 * lx;
            float b0 = bias[n], b1 = bias[n + 1];
            float2 v0 = {__uint_as_float(f2tf(acc[mi][ni][0] + b0)),
                         __uint_as_float(f2tf(acc[mi][ni][1] + b1))};
            float2 v1 = {__uint_as_float(f2tf(acc[mi][ni][2] + b0)),
                         __uint_as_float(f2tf(acc[mi][ni][3] + b1))};
            *(float2*)(C + (size_t)m * HID + n) = v0;
            *(float2*)(C + (size_t)(m + 8) * HID + n) = v1;
        }
    }
}

// ---------------------------------------------------------------------------
// Fused cross-attention v4: register-resident scores, warp-private staging,
// 64-row tiles, FOUR warp-private buffers (prefetch depth 3).
// K staged at pitch 76 (phase1 conflict-free), V at pitch 72 (phase2).
// 16 q-rows/CTA, 256 thr, 96KB smem -> 2 CTAs/SM.
// ---------------------------------------------------------------------------
#define QROWS   16
#define KP      76
#define VP      72
#define WBUF    608                   // 8 rows * 76 (max pitch)
#define NBUF    4
#define WREGION (NBUF * WBUF)         // 2432 words per warp
#define KVW_WORDS (8 * WREGION)       // 19456
#define QPITCH  68
#define PWPITCH 18
#define RED_PITCH 68

#define SM_QS   KVW_WORDS
#define SM_MSK  (SM_QS + QROWS * QPITCH)
#define SM_SRED (SM_MSK + 1024)
#define SM_PW   (SM_SRED + 128)
#define ATTN_FLOATS (SM_PW + 8 * QROWS * PWPITCH)
#define ATTN_SMEM (ATTN_FLOATS * 4)

__global__ __launch_bounds__(256, 2) void attn_kernel(const float* __restrict__ mask1,
                                                      const float* __restrict__ mask2,
                                                      float* __restrict__ out) {
    extern __shared__ float sm[];
    uint32_t* KVW = (uint32_t*)sm;             // 8 warps x 4 bufs x [8][KP]
    uint32_t* Qs  = (uint32_t*)(sm + SM_QS);   // [16][QPITCH]
    float*    msk = sm + SM_MSK;               // [1024]
    float*    sred = sm + SM_SRED;             // [16][8]
    uint32_t* Pw  = (uint32_t*)(sm + SM_PW);   // 8 x [16][PWPITCH]

    const int qb = blockIdx.x;
    const int h  = blockIdx.y;
    const int b  = blockIdx.z >> 1;
    const int st = blockIdx.z & 1;

    const float* Q    = g_qkv[st * 3];
    const float* K    = st ? g_qkv[1] : g_qkv[4];
    const float* V    = st ? g_qkv[2] : g_qkv[5];
    const float* mask = st ? mask1 : mask2;

    float* probs = out + 8388608 + (size_t)st * 67108864
                 + ((size_t)(b * NH + h) * SEQ + qb * QROWS) * SEQ;
    float* ctx = out + (size_t)st * 4194304;

    const int tid = threadIdx.x;
    const int wid = tid >> 5;
    const int lane = tid & 31;
    const int ly = lane >> 2;
    const int lx = lane & 3;
    const int wn8 = wid * 8;

    const int srow = tid >> 4;
    const int sc4 = (tid & 15) << 2;
    const uint32_t smb = (uint32_t)__cvta_generic_to_shared(sm);

    // stage this warp's 8 rows of 64-row tile `tile` into warp-private buffer
    auto stage = [&](const float* src, int tile, int buf, int pitch) {
        const uint32_t base = smb + (wid * WREGION + buf * WBUF) * 4;
#pragma unroll
        for (int i = 0; i < 4; i++) {
            int idx = lane + 32 * i;
            int r = idx >> 4, c4 = (idx & 15) << 2;
            int grow = tile * 64 + wn8 + r;
            CP_ASYNC16(base + (r * pitch + c4) * 4,
                       src + (size_t)(b * SEQ + grow) * HID + h * DH + c4);
        }
        CP_COMMIT();
    };

    // G0: mask + Q (CTA-wide); then K tiles 0,1,2 (warp-private)
    CP_ASYNC16(smb + (SM_MSK + tid * 4) * 4, mask + b * SEQ + tid * 4);
    CP_ASYNC16(smb + (SM_QS + srow * QPITCH + sc4) * 4,
               Q + (size_t)(b * SEQ + qb * QROWS + srow) * HID + h * DH + sc4);
    CP_COMMIT();
    stage(K, 0, 0, KP);
    stage(K, 1, 1, KP);
    stage(K, 2, 2, KP);

    CP_WAIT(3);          // G0 (mask+Q) done
    __syncthreads();     // Q/mask visible CTA-wide

    uint32_t aq[8][4];
#pragma unroll
    for (int ks = 0; ks < 8; ks++) {
        const int kk = ks * 8;
        aq[ks][0] = Qs[ly * QPITCH + kk + lx];
        aq[ks][1] = Qs[(ly + 8) * QPITCH + kk + lx];
        aq[ks][2] = Qs[ly * QPITCH + kk + lx + 4];
        aq[ks][3] = Qs[(ly + 8) * QPITCH + kk + lx + 4];
    }

    float acc[16][4];
#pragma unroll
    for (int j = 0; j < 16; j++)
#pragma unroll
        for (int q = 0; q < 4; q++) acc[j][q] = 0.f;

    // ---- Phase 1: 16 tiles, depth-3 prefetch, barrier-free ----
#pragma unroll
    for (int t = 0; t < 16; t++) {
        if (t < 13)      { stage(K, t + 3, (t + 3) & 3, KP); CP_WAIT(3); }
        else if (t == 13) CP_WAIT(2);
        else if (t == 14) CP_WAIT(1);
        else              CP_WAIT(0);

        const uint32_t* KB = KVW + wid * WREGION + (t & 3) * WBUF;
#pragma unroll
        for (int ks = 0; ks < 8; ks++) {
            const int kk = ks * 8;
            uint32_t bb[2];
            bb[0] = KB[ly * KP + kk + lx];
            bb[1] = KB[ly * KP + kk + lx + 4];
            mma_tf32(acc[t], aq[ks], bb);
        }
    }

    // prefetch V tiles 0,1,2 (overlaps softmax)
    stage(V, 0, 0, VP);
    stage(V, 1, 1, VP);
    stage(V, 2, 2, VP);

    // ---- scale + mask ----
#pragma unroll
    for (int j = 0; j < 16; j++) {
        const int col = wn8 + 64 * j + 2 * lx;
        float mk0 = msk[col], mk1 = msk[col + 1];
        acc[j][0] = fmaf(acc[j][0], 0.125f, mk0);
        acc[j][1] = fmaf(acc[j][1], 0.125f, mk1);
        acc[j][2] = fmaf(acc[j][2], 0.125f, mk0);
        acc[j][3] = fmaf(acc[j][3], 0.125f, mk1);
    }

    // ---- softmax on registers + tiny cross-warp reduce ----
    float m0 = -1e30f, m1 = -1e30f;
#pragma unroll
    for (int j = 0; j < 16; j++) {
        m0 = fmaxf(m0, fmaxf(acc[j][0], acc[j][1]));
        m1 = fmaxf(m1, fmaxf(acc[j][2], acc[j][3]));
    }
    m0 = fmaxf(m0, __shfl_xor_sync(0xffffffffu, m0, 1));
    m0 = fmaxf(m0, __shfl_xor_sync(0xffffffffu, m0, 2));
    m1 = fmaxf(m1, __shfl_xor_sync(0xffffffffu, m1, 1));
    m1 = fmaxf(m1, __shfl_xor_sync(0xffffffffu, m1, 2));
    if (lx == 0) {
        sred[ly * 8 + wid] = m0;
        sred[(ly + 8) * 8 + wid] = m1;
    }
    __syncthreads();
    {
        float4 a4 = *(float4*)&sred[ly * 8];
        float4 b4 = *(float4*)&sred[ly * 8 + 4];
        m0 = fmaxf(fmaxf(fmaxf(a4.x, a4.y), fmaxf(a4.z, a4.w)),
                   fmaxf(fmaxf(b4.x, b4.y), fmaxf(b4.z, b4.w)));
        a4 = *(float4*)&sred[(ly + 8) * 8];
        b4 = *(float4*)&sred[(ly + 8) * 8 + 4];
        m1 = fmaxf(fmaxf(fmaxf(a4.x, a4.y), fmaxf(a4.z, a4.w)),
                   fmaxf(fmaxf(b4.x, b4.y), fmaxf(b4.z, b4.w)));
    }

    float s0 = 0.f, s1 = 0.f;
#pragma unroll
    for (int j = 0; j < 16; j++) {
        acc[j][0] = fast_exp(acc[j][0] - m0);
        acc[j][1] = fast_exp(acc[j][1] - m0);
        acc[j][2] = fast_exp(acc[j][2] - m1);
        acc[j][3] = fast_exp(acc[j][3] - m1);
        s0 += acc[j][0] + acc[j][1];
        s1 += acc[j][2] + acc[j][3];
    }
    s0 += __shfl_xor_sync(0xffffffffu, s0, 1);
    s0 += __shfl_xor_sync(0xffffffffu, s0, 2);
    s1 += __shfl_xor_sync(0xffffffffu, s1, 1);
    s1 += __shfl_xor_sync(0xffffffffu, s1, 2);
    __syncthreads();
    if (lx == 0) {
        sred[ly * 8 + wid] = s0;
        sred[(ly + 8) * 8 + wid] = s1;
    }
    __syncthreads();
    float inv0, inv1;
    {
        float4 a4 = *(float4*)&sred[ly * 8];
        float4 b4 = *(float4*)&sred[ly * 8 + 4];
        inv0 = 1.f / (a4.x + a4.y + a4.z + a4.w + b4.x + b4.y + b4.z + b4.w);
        a4 = *(float4*)&sred[(ly + 8) * 8];
        b4 = *(float4*)&sred[(ly + 8) * 8 + 4];
        inv1 = 1.f / (a4.x + a4.y + a4.z + a4.w + b4.x + b4.y + b4.z + b4.w);
    }

    // ---- write probs + convert P to tf32 in registers ----
#pragma unroll
    for (int j = 0; j < 16; j++) {
        const int col = wn8 + 64 * j + 2 * lx;
        float p0 = acc[j][0] * inv0, p1 = acc[j][1] * inv0;
        float p2 = acc[j][2] * inv1, p3 = acc[j][3] * inv1;
        float2 v0 = {p0, p1};
        float2 v1 = {p2, p3};
        *(float2*)&probs[ly * 1024 + col] = v0;
        *(float2*)&probs[(ly + 8) * 1024 + col] = v1;
        acc[j][0] = __uint_as_float(f2tf(p0));
        acc[j][1] = __uint_as_float(f2tf(p1));
        acc[j][2] = __uint_as_float(f2tf(p2));
        acc[j][3] = __uint_as_float(f2tf(p3));
    }

    // ---- Phase 2: 16 tiles, depth-3 prefetch, warp-private ----
    float pacc[8][4];
#pragma unroll
    for (int ni = 0; ni < 8; ni++)
#pragma unroll
        for (int q = 0; q < 4; q++) pacc[ni][q] = 0.f;

    uint32_t* Pme = Pw + wid * (QROWS * PWPITCH);
    const uint32_t* au = (const uint32_t*)acc;

#pragma unroll
    for (int t = 0; t < 16; t++) {
        if (t < 13)      { stage(V, t + 3, (t + 3) & 3, VP); CP_WAIT(3); }
        else if (t == 13) CP_WAIT(2);
        else if (t == 14) CP_WAIT(1);
        else              CP_WAIT(0);

        // patch this warp's P col-group t into A-fragment layout
        {
            uint2 t0 = {au[t * 4 + 0], au[t * 4 + 1]};
            uint2 t1 = {au[t * 4 + 2], au[t * 4 + 3]};
            *(uint2*)&Pme[ly * PWPITCH + 2 * lx] = t0;
            *(uint2*)&Pme[(ly + 8) * PWPITCH + 2 * lx] = t1;
        }
        __syncwarp();

        uint32_t a[4];
        a[0] = Pme[ly * PWPITCH + lx];
        a[1] = Pme[(ly + 8) * PWPITCH + lx];
        a[2] = Pme[ly * PWPITCH + lx + 4];
        a[3] = Pme[(ly + 8) * PWPITCH + lx + 4];

        const uint32_t* VB = KVW + wid * WREGION + (t & 3) * WBUF;
#pragma unroll
        for (int ni = 0; ni < 8; ni++) {
            uint32_t bb[2];
            bb[0] = VB[lx * VP + ni * 8 + ly];
            bb[1] = VB[(lx + 4) * VP + ni * 8 + ly];
            mma_tf32(pacc[ni], a, bb);
        }
        __syncwarp();   // Pme reads done before next iteration's patch
    }

    // ---- ctx reduce: partials into own KV region ----
    {
        float* red_w = sm + wid * WREGION;
#pragma unroll
        for (int ni = 0; ni < 8; ni++) {
            float2 v0 = {pacc[ni][0], pacc[ni][1]};
            float2 v1 = {pacc[ni][2], pacc[ni][3]};
            *(float2*)&red_w[ly * RED_PITCH + ni * 8 + 2 * lx] = v0;
            *(float2*)&red_w[(ly + 8) * RED_PITCH + ni * 8 + 2 * lx] = v1;
        }
    }
    __syncthreads();

    {
        const int row = tid >> 4;
        const int col = (tid & 15) << 2;
        float s0v = 0.f, s1v = 0.f, s2v = 0.f, s3v = 0.f;
#pragma unroll
        for (int w = 0; w < 8; w++) {
            const float* rp = sm + w * WREGION + row * RED_PITCH + col;
            s0v += rp[0]; s1v += rp[1]; s2v += rp[2]; s3v += rp[3];
        }
        float4 v = {s0v, s1v, s2v, s3v};
        *(float4*)(ctx + (size_t)(b * SEQ + qb * QROWS + row) * HID + h * DH + col) = v;
    }
}

// ---------------------------------------------------------------------------
extern "C" void kernel_launch(void* const* d_in, const int* in_sizes, int n_in,
                              void* d_out, int out_size) {
    (void)in_sizes; (void)n_in; (void)out_size;

    const float* m1 = (const float*)d_in[1];
    const float* m2 = (const float*)d_in[3];

    QKVArgs a;
    a.x[0] = (const float*)d_in[0];
    a.x[1] = (const float*)d_in[2];
    for (int i = 0; i < 6; i++) {
        a.w[i] = (const float*)d_in[4 + 2 * i];
        a.b[i] = (const float*)d_in[5 + 2 * i];
    }

    cudaFuncSetAttribute(qkv_gemm, cudaFuncAttributeMaxDynamicSharedMemorySize,
                         GEMM_SMEM);
    cudaFuncSetAttribute(attn_kernel, cudaFuncAttributeMaxDynamicSharedMemorySize,
                         ATTN_SMEM);

    conv_tf32<<<dim3(1024, 8), 256>>>(a);
    qkv_gemm<<<dim3(8, 32, 6), 256, GEMM_SMEM>>>(a);
    attn_kernel<<<dim3(64, 16, 8), 256, ATTN_SMEM>>>(m1, m2, (float*)d_out);
}

// round 17
// speedup vs baseline: 1.7996x; 1.0714x over previous
#include <cuda_runtime.h>
#include <cstdint>

#define HID 1024
#define SEQ 1024
#define NB  4
#define NH  16
#define DH  64

// Scratch: q/k/v outputs (tf32-rounded) + tf32-preconverted inputs.
__device__ float g_qkv[6][NB * SEQ * HID];
__device__ float g_xc[2][NB * SEQ * HID];
__device__ float g_wc[6][HID * HID];

struct QKVArgs {
    const float* x[2];
    const float* w[6];
    const float* b[6];
};

__device__ __forceinline__ uint32_t f2tf(float x) {
    uint32_t t;
    asm("cvt.rna.tf32.f32 %0, %1;" : "=r"(t) : "f"(x));
    return t;
}

__device__ __forceinline__ void mma_tf32(float* c, const uint32_t* a, const uint32_t* b) {
    asm volatile(
        "mma.sync.aligned.m16n8k8.row.col.f32.tf32.tf32.f32 "
        "{%0,%1,%2,%3}, {%4,%5,%6,%7}, {%8,%9}, {%0,%1,%2,%3};\n"
        : "+f"(c[0]), "+f"(c[1]), "+f"(c[2]), "+f"(c[3])
        : "r"(a[0]), "r"(a[1]), "r"(a[2]), "r"(a[3]), "r"(b[0]), "r"(b[1]));
}

#define CP_ASYNC16(saddr, gptr) \
    asm volatile("cp.async.cg.shared.global [%0], [%1], 16;\n" :: "r"(saddr), "l"(gptr))
#define CP_COMMIT() asm volatile("cp.async.commit_group;\n" ::: "memory")
#define CP_WAIT(n)  asm volatile("cp.async.wait_group %0;\n" :: "n"(n) : "memory")

__device__ __forceinline__ float fast_exp(float x) {
    x = fmaxf(x, -80.f);
    float t = x * 1.44269504f;
    float r = rintf(t);
    float y = (t - r) * 0.69314718f;
    float p = 8.3333333e-3f;
    p = fmaf(p, y, 4.1666667e-2f);
    p = fmaf(p, y, 1.6666667e-1f);
    p = fmaf(p, y, 5.0e-1f);
    p = fmaf(p, y, 1.0f);
    p = fmaf(p, y, 1.0f);
    return __int_as_float(__float_as_int(p) + (((int)r) << 23));
}

// ---------------------------------------------------------------------------
// Pre-convert X (2x) and W (6x) to tf32 once. (unchanged)
// ---------------------------------------------------------------------------
__global__ __launch_bounds__(256) void conv_tf32(QKVArgs args) {
    const int seg = blockIdx.y;
    const float* src;
    float* dst;
    int n4;
    if (seg < 2) { src = args.x[seg]; dst = g_xc[seg]; n4 = NB * SEQ * HID / 4; }
    else         { src = args.w[seg - 2]; dst = g_wc[seg - 2]; n4 = HID * HID / 4; }
    const int stride = gridDim.x * blockDim.x;
    for (int i = blockIdx.x * blockDim.x + threadIdx.x; i < n4; i += stride) {
        float4 v = ((const float4*)src)[i];
        uint4 t = {f2tf(v.x), f2tf(v.y), f2tf(v.z), f2tf(v.w)};
        ((uint4*)dst)[i] = t;
    }
}

// ---------------------------------------------------------------------------
// QKV projection: 128x128x16, 4-stage cp.async pipeline. (unchanged)
// ---------------------------------------------------------------------------
#define STAGES  4
#define BK      16
#define APITCH  20
#define BPITCH  136
#define A_ST    (128 * APITCH)
#define B_ST    (BK * BPITCH)
#define ST_WORDS (A_ST + B_ST)
#define GEMM_SMEM (STAGES * ST_WORDS * 4)

__global__ __launch_bounds__(256, 2) void qkv_gemm(QKVArgs args) {
    extern __shared__ uint32_t gsm[];

    const int p = blockIdx.z;
    const float* X    = g_xc[p / 3];
    const float* W    = g_wc[p];
    const float* bias = args.b[p];
    float* C = g_qkv[p];

    const int tid = threadIdx.x;
    const int wid = tid >> 5;
    const int lane = tid & 31;
    const int ly = lane >> 2;
    const int lx = lane & 3;
    const int wm = (wid & 1) * 64;
    const int wn = (wid >> 1) * 32;
    const int bm = blockIdx.y << 7;
    const int bn = blockIdx.x << 7;

    const uint32_t smb = (uint32_t)__cvta_generic_to_shared(gsm);

    auto issue = [&](int s, int k0) {
        const uint32_t base = smb + s * (ST_WORDS * 4);
#pragma unroll
        for (int i = 0; i < 2; i++) {
            int c = tid + i * 256;
            int row = c >> 2, kc = (c & 3) << 2;
            CP_ASYNC16(base + (row * APITCH + kc) * 4,
                       X + (size_t)(bm + row) * HID + k0 + kc);
        }
#pragma unroll
        for (int i = 0; i < 2; i++) {
            int c = tid + i * 256;
            int kr = c >> 5, nc = (c & 31) << 2;
            CP_ASYNC16(base + (A_ST + kr * BPITCH + nc) * 4,
                       W + (size_t)(k0 + kr) * HID + bn + nc);
        }
        CP_COMMIT();
    };

    issue(0, 0);
    issue(1, BK);
    issue(2, 2 * BK);

    float acc[4][4][4];
#pragma unroll
    for (int i = 0; i < 4; i++)
#pragma unroll
        for (int j = 0; j < 4; j++)
#pragma unroll
            for (int q = 0; q < 4; q++) acc[i][j][q] = 0.f;

    const int NKT = HID / BK;
    for (int kt = 0; kt < NKT; kt++) {
        CP_WAIT(2);
        __syncthreads();
        if (kt + 3 < NKT) issue((kt + 3) & 3, (kt + 3) * BK);
        else CP_COMMIT();

        const uint32_t* As = gsm + (kt & 3) * ST_WORDS;
        const uint32_t* Bs = As + A_ST;

#pragma unroll
        for (int ks = 0; ks < 2; ks++) {
            const int kk = ks * 8;
            uint32_t a[4][4], b[4][2];
#pragma unroll
            for (int mi = 0; mi < 4; mi++) {
                int m = wm + mi * 16;
                a[mi][0] = As[(m + ly) * APITCH + kk + lx];
                a[mi][1] = As[(m + ly + 8) * APITCH + kk + lx];
                a[mi][2] = As[(m + ly) * APITCH + kk + lx + 4];
                a[mi][3] = As[(m + ly + 8) * APITCH + kk + lx + 4];
            }
#pragma unroll
            for (int ni = 0; ni < 4; ni++) {
                int n = wn + ni * 8;
                b[ni][0] = Bs[(kk + lx) * BPITCH + n + ly];
                b[ni][1] = Bs[(kk + lx + 4) * BPITCH + n + ly];
            }
#pragma unroll
            for (int mi = 0; mi < 4; mi++)
#pragma unroll
                for (int ni = 0; ni < 4; ni++)
                    mma_tf32(acc[mi][ni], a[mi], b[ni]);
        }
    }

#pragma unroll
    for (int mi = 0; mi < 4; mi++) {
#pragma unroll
        for (int ni = 0; ni < 4; ni++) {
            int m = bm + wm + mi * 16 + ly;
            int n = bn + wn + ni * 8 + 2 * lx;
            float b0 = bias[n], b1 = bias[n + 1];
            float2 v0 = {__uint_as_float(f2tf(acc[mi][ni][0] + b0)),
                         __uint_as_float(f2tf(acc[mi][ni][1] + b1))};
            float2 v1 = {__uint_as_float(f2tf(acc[mi][ni][2] + b0)),
                         __uint_as_float(f2tf(acc[mi][ni][3] + b1))};
            *(float2*)(C + (size_t)m * HID + n) = v0;
            *(float2*)(C + (size_t)(m + 8) * HID + n) = v1;
        }
    }
}

// ---------------------------------------------------------------------------
// Fused cross-attention v5: QROWS=32 (halves K/V L2 traffic), register-
// resident scores (128 regs), warp-private depth-3 staging, barrier-free
// mainloops. 256 thr, 1 CTA/SM.
// ---------------------------------------------------------------------------
#define QROWS   32
#define KP      76
#define VP      72
#define WBUF    608                   // 8 rows * 76 (max pitch)
#define NBUF    4
#define WREGION (NBUF * WBUF)         // 2432 words per warp
#define KVW_WORDS (8 * WREGION)       // 19456
#define QPITCH  68
#define PWPITCH 12
#define RED_PITCH 68

#define SM_QS   KVW_WORDS
#define SM_MSK  (SM_QS + QROWS * QPITCH)
#define SM_SRED (SM_MSK + 1024)
#define SM_PW   (SM_SRED + 256)
#define ATTN_FLOATS (SM_PW + 8 * QROWS * PWPITCH)
#define ATTN_SMEM (ATTN_FLOATS * 4)

__global__ __launch_bounds__(256, 1) void attn_kernel(const float* __restrict__ mask1,
                                                      const float* __restrict__ mask2,
                                                      float* __restrict__ out) {
    extern __shared__ float sm[];
    uint32_t* KVW = (uint32_t*)sm;             // 8 warps x 4 bufs x [8][KP]
    uint32_t* Qs  = (uint32_t*)(sm + SM_QS);   // [32][QPITCH]
    float*    msk = sm + SM_MSK;               // [1024]
    float*    sred = sm + SM_SRED;             // [32][8]
    uint32_t* Pw  = (uint32_t*)(sm + SM_PW);   // 8 x [32][PWPITCH]

    const int qb = blockIdx.x;          // 0..31 (32-row q blocks)
    const int h  = blockIdx.y;
    const int b  = blockIdx.z >> 1;
    const int st = blockIdx.z & 1;

    const float* Q    = g_qkv[st * 3];
    const float* K    = st ? g_qkv[1] : g_qkv[4];
    const float* V    = st ? g_qkv[2] : g_qkv[5];
    const float* mask = st ? mask1 : mask2;

    float* probs = out + 8388608 + (size_t)st * 67108864
                 + ((size_t)(b * NH + h) * SEQ + qb * QROWS) * SEQ;
    float* ctx = out + (size_t)st * 4194304;

    const int tid = threadIdx.x;
    const int wid = tid >> 5;
    const int lane = tid & 31;
    const int ly = lane >> 2;
    const int lx = lane & 3;
    const int wn8 = wid * 8;

    const uint32_t smb = (uint32_t)__cvta_generic_to_shared(sm);

    // stage this warp's 8 rows of 64-row tile `tile` into warp-private buffer
    auto stage = [&](const float* src, int tile, int buf, int pitch) {
        const uint32_t base = smb + (wid * WREGION + buf * WBUF) * 4;
#pragma unroll
        for (int i = 0; i < 4; i++) {
            int idx = lane + 32 * i;
            int r = idx >> 4, c4 = (idx & 15) << 2;
            int grow = tile * 64 + wn8 + r;
            CP_ASYNC16(base + (r * pitch + c4) * 4,
                       src + (size_t)(b * SEQ + grow) * HID + h * DH + c4);
        }
        CP_COMMIT();
    };

    // G0: mask + Q (CTA-wide); then K tiles 0,1,2 (warp-private)
    CP_ASYNC16(smb + (SM_MSK + tid * 4) * 4, mask + b * SEQ + tid * 4);
#pragma unroll
    for (int i = 0; i < 2; i++) {
        int idx = tid + i * 256;
        int r = idx >> 4, c4 = (idx & 15) << 2;
        CP_ASYNC16(smb + (SM_QS + r * QPITCH + c4) * 4,
                   Q + (size_t)(b * SEQ + qb * QROWS + r) * HID + h * DH + c4);
    }
    CP_COMMIT();
    stage(K, 0, 0, KP);
    stage(K, 1, 1, KP);
    stage(K, 2, 2, KP);

    CP_WAIT(3);          // G0 (mask+Q) done
    __syncthreads();     // Q/mask visible CTA-wide

    // hoisted Q A-fragments for both m16 halves
    uint32_t aq[2][8][4];
#pragma unroll
    for (int mh = 0; mh < 2; mh++)
#pragma unroll
        for (int ks = 0; ks < 8; ks++) {
            const int kk = ks * 8;
            const int r0 = mh * 16 + ly;
            aq[mh][ks][0] = Qs[r0 * QPITCH + kk + lx];
            aq[mh][ks][1] = Qs[(r0 + 8) * QPITCH + kk + lx];
            aq[mh][ks][2] = Qs[r0 * QPITCH + kk + lx + 4];
            aq[mh][ks][3] = Qs[(r0 + 8) * QPITCH + kk + lx + 4];
        }

    float acc[16][2][4];
#pragma unroll
    for (int j = 0; j < 16; j++)
#pragma unroll
        for (int mh = 0; mh < 2; mh++)
#pragma unroll
            for (int q = 0; q < 4; q++) acc[j][mh][q] = 0.f;

    // ---- Phase 1: 16 tiles, depth-3 prefetch, barrier-free ----
#pragma unroll
    for (int t = 0; t < 16; t++) {
        if (t < 13)      { stage(K, t + 3, (t + 3) & 3, KP); CP_WAIT(3); }
        else if (t == 13) CP_WAIT(2);
        else if (t == 14) CP_WAIT(1);
        else              CP_WAIT(0);

        const uint32_t* KB = KVW + wid * WREGION + (t & 3) * WBUF;
#pragma unroll
        for (int ks = 0; ks < 8; ks++) {
            const int kk = ks * 8;
            uint32_t bb[2];
            bb[0] = KB[ly * KP + kk + lx];
            bb[1] = KB[ly * KP + kk + lx + 4];
            mma_tf32(acc[t][0], aq[0][ks], bb);
            mma_tf32(acc[t][1], aq[1][ks], bb);
        }
    }

    // prefetch V tiles 0,1,2 (overlaps softmax)
    stage(V, 0, 0, VP);
    stage(V, 1, 1, VP);
    stage(V, 2, 2, VP);

    // ---- scale + mask ----
#pragma unroll
    for (int j = 0; j < 16; j++) {
        const int col = wn8 + 64 * j + 2 * lx;
        float mk0 = msk[col], mk1 = msk[col + 1];
#pragma unroll
        for (int mh = 0; mh < 2; mh++) {
            acc[j][mh][0] = fmaf(acc[j][mh][0], 0.125f, mk0);
            acc[j][mh][1] = fmaf(acc[j][mh][1], 0.125f, mk1);
            acc[j][mh][2] = fmaf(acc[j][mh][2], 0.125f, mk0);
            acc[j][mh][3] = fmaf(acc[j][mh][3], 0.125f, mk1);
        }
    }

    // ---- softmax on registers: 4 row-chunks per thread ----
    // rows: m[0]=ly, m[1]=ly+8, m[2]=ly+16, m[3]=ly+24
    float mrow[4] = {-1e30f, -1e30f, -1e30f, -1e30f};
#pragma unroll
    for (int j = 0; j < 16; j++)
#pragma unroll
        for (int mh = 0; mh < 2; mh++) {
            mrow[2 * mh + 0] = fmaxf(mrow[2 * mh + 0], fmaxf(acc[j][mh][0], acc[j][mh][1]));
            mrow[2 * mh + 1] = fmaxf(mrow[2 * mh + 1], fmaxf(acc[j][mh][2], acc[j][mh][3]));
        }
#pragma unroll
    for (int r = 0; r < 4; r++) {
        mrow[r] = fmaxf(mrow[r], __shfl_xor_sync(0xffffffffu, mrow[r], 1));
        mrow[r] = fmaxf(mrow[r], __shfl_xor_sync(0xffffffffu, mrow[r], 2));
    }
    if (lx == 0) {
        sred[ly * 8 + wid] = mrow[0];
        sred[(ly + 8) * 8 + wid] = mrow[1];
        sred[(ly + 16) * 8 + wid] = mrow[2];
        sred[(ly + 24) * 8 + wid] = mrow[3];
    }
    __syncthreads();
#pragma unroll
    for (int r = 0; r < 4; r++) {
        float4 a4 = *(float4*)&sred[(ly + r * 8) * 8];
        float4 b4 = *(float4*)&sred[(ly + r * 8) * 8 + 4];
        mrow[r] = fmaxf(fmaxf(fmaxf(a4.x, a4.y), fmaxf(a4.z, a4.w)),
                        fmaxf(fmaxf(b4.x, b4.y), fmaxf(b4.z, b4.w)));
    }

    float srow[4] = {0.f, 0.f, 0.f, 0.f};
#pragma unroll
    for (int j = 0; j < 16; j++)
#pragma unroll
        for (int mh = 0; mh < 2; mh++) {
            acc[j][mh][0] = fast_exp(acc[j][mh][0] - mrow[2 * mh + 0]);
            acc[j][mh][1] = fast_exp(acc[j][mh][1] - mrow[2 * mh + 0]);
            acc[j][mh][2] = fast_exp(acc[j][mh][2] - mrow[2 * mh + 1]);
            acc[j][mh][3] = fast_exp(acc[j][mh][3] - mrow[2 * mh + 1]);
            srow[2 * mh + 0] += acc[j][mh][0] + acc[j][mh][1];
            srow[2 * mh + 1] += acc[j][mh][2] + acc[j][mh][3];
        }
#pragma unroll
    for (int r = 0; r < 4; r++) {
        srow[r] += __shfl_xor_sync(0xffffffffu, srow[r], 1);
        srow[r] += __shfl_xor_sync(0xffffffffu, srow[r], 2);
    }
    __syncthreads();   // everyone done reading maxes from sred
    if (lx == 0) {
        sred[ly * 8 + wid] = srow[0];
        sred[(ly + 8) * 8 + wid] = srow[1];
        sred[(ly + 16) * 8 + wid] = srow[2];
        sred[(ly + 24) * 8 + wid] = srow[3];
    }
    __syncthreads();
    float inv[4];
#pragma unroll
    for (int r = 0; r < 4; r++) {
        float4 a4 = *(float4*)&sred[(ly + r * 8) * 8];
        float4 b4 = *(float4*)&sred[(ly + r * 8) * 8 + 4];
        inv[r] = 1.f / (a4.x + a4.y + a4.z + a4.w + b4.x + b4.y + b4.z + b4.w);
    }

    // ---- write probs + convert P to tf32 in registers ----
#pragma unroll
    for (int j = 0; j < 16; j++) {
        const int col = wn8 + 64 * j + 2 * lx;
#pragma unroll
        for (int mh = 0; mh < 2; mh++) {
            float p0 = acc[j][mh][0] * inv[2 * mh + 0];
            float p1 = acc[j][mh][1] * inv[2 * mh + 0];
            float p2 = acc[j][mh][2] * inv[2 * mh + 1];
            float p3 = acc[j][mh][3] * inv[2 * mh + 1];
            float2 v0 = {p0, p1};
            float2 v1 = {p2, p3};
            *(float2*)&probs[(mh * 16 + ly) * 1024 + col] = v0;
            *(float2*)&probs[(mh * 16 + ly + 8) * 1024 + col] = v1;
            acc[j][mh][0] = __uint_as_float(f2tf(p0));
            acc[j][mh][1] = __uint_as_float(f2tf(p1));
            acc[j][mh][2] = __uint_as_float(f2tf(p2));
            acc[j][mh][3] = __uint_as_float(f2tf(p3));
        }
    }

    // ---- Phase 2: 16 tiles, depth-3 prefetch, warp-private k-split ----
    float pacc[2][8][4];
#pragma unroll
    for (int mh = 0; mh < 2; mh++)
#pragma unroll
        for (int ni = 0; ni < 8; ni++)
#pragma unroll
            for (int q = 0; q < 4; q++) pacc[mh][ni][q] = 0.f;

    uint32_t* Pme = Pw + wid * (QROWS * PWPITCH);
    const uint32_t* au = (const uint32_t*)acc;

#pragma unroll
    for (int t = 0; t < 16; t++) {
        if (t < 13)      { stage(V, t + 3, (t + 3) & 3, VP); CP_WAIT(3); }
        else if (t == 13) CP_WAIT(2);
        else if (t == 14) CP_WAIT(1);
        else              CP_WAIT(0);

        // patch this warp's P col-group t (both m halves) into A-frag layout
#pragma unroll
        for (int mh = 0; mh < 2; mh++) {
            const int base = (t * 2 + mh) * 4;
            uint2 t0 = {au[base + 0], au[base + 1]};
            uint2 t1 = {au[base + 2], au[base + 3]};
            *(uint2*)&Pme[(mh * 16 + ly) * PWPITCH + 2 * lx] = t0;
            *(uint2*)&Pme[(mh * 16 + ly + 8) * PWPITCH + 2 * lx] = t1;
        }
        __syncwarp();

        uint32_t a[2][4];
#pragma unroll
        for (int mh = 0; mh < 2; mh++) {
            a[mh][0] = Pme[(mh * 16 + ly) * PWPITCH + lx];
            a[mh][1] = Pme[(mh * 16 + ly + 8) * PWPITCH + lx];
            a[mh][2] = Pme[(mh * 16 + ly) * PWPITCH + lx + 4];
            a[mh][3] = Pme[(mh * 16 + ly + 8) * PWPITCH + lx + 4];
        }

        const uint32_t* VB = KVW + wid * WREGION + (t & 3) * WBUF;
#pragma unroll
        for (int ni = 0; ni < 8; ni++) {
            uint32_t bb[2];
            bb[0] = VB[lx * VP + ni * 8 + ly];
            bb[1] = VB[(lx + 4) * VP + ni * 8 + ly];
            mma_tf32(pacc[0][ni], a[0], bb);
            mma_tf32(pacc[1][ni], a[1], bb);
        }
        __syncwarp();   // Pme reads done before next iteration's patch
    }

    // ---- ctx reduce: partials into own KV region (2432 >= 32*68) ----
    {
        float* red_w = sm + wid * WREGION;
#pragma unroll
        for (int mh = 0; mh < 2; mh++)
#pragma unroll
            for (int ni = 0; ni < 8; ni++) {
                float2 v0 = {pacc[mh][ni][0], pacc[mh][ni][1]};
                float2 v1 = {pacc[mh][ni][2], pacc[mh][ni][3]};
                *(float2*)&red_w[(mh * 16 + ly) * RED_PITCH + ni * 8 + 2 * lx] = v0;
                *(float2*)&red_w[(mh * 16 + ly + 8) * RED_PITCH + ni * 8 + 2 * lx] = v1;
            }
    }
    __syncthreads();

    {
        const int row = tid >> 3;            // 0..31
        const int col = (tid & 7) << 3;      // 0..56 (8 floats per thread)
        float s[8] = {0.f, 0.f, 0.f, 0.f, 0.f, 0.f, 0.f, 0.f};
#pragma unroll
        for (int w = 0; w < 8; w++) {
            const float* rp = sm + w * WREGION + row * RED_PITCH + col;
#pragma unroll
            for (int q = 0; q < 8; q++) s[q] += rp[q];
        }
        float4 v0 = {s[0], s[1], s[2], s[3]};
        float4 v1 = {s[4], s[5], s[6], s[7]};
        float* dst = ctx + (size_t)(b * SEQ + qb * QROWS + row) * HID + h * DH + col;
        *(float4*)dst = v0;
        *(float4*)(dst + 4) = v1;
    }
}

// ---------------------------------------------------------------------------
extern "C" void kernel_launch(void* const* d_in, const int* in_sizes, int n_in,
                              void* d_out, int out_size) {
    (void)in_sizes; (void)n_in; (void)out_size;

    const float* m1 = (const float*)d_in[1];
    const float* m2 = (const float*)d_in[3];

    QKVArgs a;
    a.x[0] = (const float*)d_in[0];
    a.x[1] = (const float*)d_in[2];
    for (int i = 0; i < 6; i++) {
        a.w[i] = (const float*)d_in[4 + 2 * i];
        a.b[i] = (const float*)d_in[5 + 2 * i];
    }

    cudaFuncSetAttribute(qkv_gemm, cudaFuncAttributeMaxDynamicSharedMemorySize,
                         GEMM_SMEM);
    cudaFuncSetAttribute(attn_kernel, cudaFuncAttributeMaxDynamicSharedMemorySize,
                         ATTN_SMEM);

    conv_tf32<<<dim3(1024, 8), 256>>>(a);
    qkv_gemm<<<dim3(8, 32, 6), 256, GEMM_SMEM>>>(a);
    attn_kernel<<<dim3(32, 16, 8), 256, ATTN_SMEM>>>(m1, m2, (float*)d_out);
}